// round 12
// baseline (speedup 1.0000x reference)
#include <cuda_runtime.h>
#include <cuda_fp16.h>
#include <math.h>
#include <stdint.h>

#define BATCH 2
#define SEQ 1024
#define HID 4096
#define NH 32
#define NKV 2
#define HD 128
#define FFN 13696
#define QKV_DIM ((NH + 2*NKV)*HD)   // 4608
#define M_ROWS (BATCH*SEQ)          // 2048
#define EPSV 1e-5f
#define V_OFF ((NH+NKV)*HD)         // 4352
#define K_OFF (NH*HD)               // 4096
#define K2H (2*HID)
#define LO_SCALE 4096.0f            // 2^12
#define LO_INV   2.44140625e-4f     // 2^-12

// ------------------------- scratch (device globals) -------------------------
__device__ float g_qkv[(size_t)M_ROWS * QKV_DIM];
__device__ float g_attnout[(size_t)M_ROWS * HID];
__device__ float g_hidden[(size_t)M_ROWS * HID];
__device__ float g_inter[(size_t)M_ROWS * 2 * FFN];
// fp16 weights: QKV/O planar split [hi | lo*2^12]; FFN single-plane fp16
__device__ __half g_wqkvh[(size_t)QKV_DIM * K2H];
__device__ __half g_woh[(size_t)HID * K2H];
__device__ __half g_w14h[(size_t)(2*FFN) * HID];
__device__ __half g_w41h[(size_t)HID * FFN];
// fp16 single activations
__device__ __half g_xh[(size_t)M_ROWS * HID];
__device__ __half g_ah[(size_t)M_ROWS * HID];
__device__ __half g_yh[(size_t)M_ROWS * HID];
__device__ __half g_gh[(size_t)M_ROWS * FFN];

// ------------------------- PTX helpers -------------------------
__device__ __forceinline__ uint32_t smem_u32(const void* p) {
    uint32_t a;
    asm("{ .reg .u64 t; cvta.to.shared.u64 t, %1; cvt.u32.u64 %0, t; }" : "=r"(a) : "l"(p));
    return a;
}
__device__ __forceinline__ void cp16(uint32_t s, const void* g) {
    asm volatile("cp.async.cg.shared.global [%0], [%1], 16;" :: "r"(s), "l"(g));
}
__device__ __forceinline__ void ldsm4(uint32_t* r, uint32_t addr) {
    asm volatile("ldmatrix.sync.aligned.m8n8.x4.shared.b16 {%0,%1,%2,%3}, [%4];"
                 : "=r"(r[0]), "=r"(r[1]), "=r"(r[2]), "=r"(r[3]) : "r"(addr));
}
__device__ __forceinline__ void mma_f16(float* c, const uint32_t* a, uint32_t b0, uint32_t b1) {
    asm volatile(
        "mma.sync.aligned.m16n8k16.row.col.f32.f16.f16.f32 "
        "{%0,%1,%2,%3}, {%4,%5,%6,%7}, {%8,%9}, {%0,%1,%2,%3};"
        : "+f"(c[0]), "+f"(c[1]), "+f"(c[2]), "+f"(c[3])
        : "r"(a[0]), "r"(a[1]), "r"(a[2]), "r"(a[3]), "r"(b0), "r"(b1));
}

// ------------------------- misc helpers -------------------------
__device__ __forceinline__ float warp_sum(float v) {
#pragma unroll
    for (int o = 16; o > 0; o >>= 1) v += __shfl_xor_sync(0xffffffffu, v, o);
    return v;
}
// fp16 split with lo-plane scaled by 2^12 (keeps lo in fp16 normal range)
__device__ __forceinline__ void split4h_scaled(float4 v, uint2& hi, uint2& lo) {
    union { uint2 u; __half h[4]; } H, L;
    float f[4] = {v.x, v.y, v.z, v.w};
#pragma unroll
    for (int k = 0; k < 4; k++) {
        __half h = __float2half_rn(f[k]);
        H.h[k] = h;
        L.h[k] = __float2half_rn((f[k] - __half2float(h)) * LO_SCALE);
    }
    hi = H.u; lo = L.u;
}
__device__ __forceinline__ uint2 pack4h(float4 v) {
    union { uint2 u; __half h[4]; } H;
    H.h[0] = __float2half_rn(v.x); H.h[1] = __float2half_rn(v.y);
    H.h[2] = __float2half_rn(v.z); H.h[3] = __float2half_rn(v.w);
    return H.u;
}

// ------------------------- weight conversion kernels -------------------------
__global__ void split_planar_f16(const float* __restrict__ in,
                                 __half* __restrict__ out,
                                 long long n4, int kq) {
    long long i = (long long)blockIdx.x * blockDim.x + threadIdx.x;
    if (i >= n4) return;
    float4 v = ((const float4*)in)[i];
    uint2 hi, lo;
    split4h_scaled(v, hi, lo);
    long long n = i / kq;
    long long hidx = i + n * kq;
    ((uint2*)out)[hidx] = hi;
    ((uint2*)out)[hidx + kq] = lo;
}
__global__ void round_f16_kernel(const float* __restrict__ in,
                                 __half* __restrict__ out, long long n4) {
    long long i = (long long)blockIdx.x * blockDim.x + threadIdx.x;
    if (i >= n4) return;
    ((uint2*)out)[i] = pack4h(((const float4*)in)[i]);
}

// ------------------------- fused (add+)rmsnorm -> fp16 single -------------------------
__global__ void __launch_bounds__(256) fused_norm_kernel(
    const float* __restrict__ res, const float* __restrict__ x,
    const float* __restrict__ w, float* __restrict__ hid_out,
    __half* __restrict__ yh) {
    __shared__ __align__(16) float buf[HID];
    __shared__ float red[8];
    int row = blockIdx.x;
    size_t base = (size_t)row * HID;
    const float4* x4 = (const float4*)(x + base);
    const float4* r4 = res ? (const float4*)(res + base) : nullptr;
    float4* b4 = (float4*)buf;

    float ss = 0.f;
    for (int i = threadIdx.x; i < HID/4; i += 256) {
        float4 v = x4[i];
        if (r4) { float4 rr = r4[i]; v.x += rr.x; v.y += rr.y; v.z += rr.z; v.w += rr.w; }
        b4[i] = v;
        ss += v.x*v.x + v.y*v.y + v.z*v.z + v.w*v.w;
    }
    ss = warp_sum(ss);
    if ((threadIdx.x & 31) == 0) red[threadIdx.x >> 5] = ss;
    __syncthreads();
    float tot = 0.f;
#pragma unroll
    for (int i = 0; i < 8; i++) tot += red[i];
    float inv = rsqrtf(tot / (float)HID + EPSV);

    float4* h4 = hid_out ? (float4*)(hid_out + base) : nullptr;
    const float4* w4 = (const float4*)w;
    uint2* y2 = (uint2*)(yh + base);
    for (int i = threadIdx.x; i < HID/4; i += 256) {
        float4 v = b4[i];
        if (h4) h4[i] = v;
        float4 ww = w4[i];
        float4 o;
        o.x = v.x * inv * ww.x; o.y = v.y * inv * ww.y;
        o.z = v.z * inv * ww.z; o.w = v.w * inv * ww.w;
        y2[i] = pack4h(o);
    }
}

// ------------------------- fp16 HMMA GEMM (R9 config, NPH phases) -------------------------
#define NSTAGE 3
#define STAGE_BYTES 32768
#define GEMM_SMEM (NSTAGE * STAGE_BYTES + 1024)

template<int NPH>
__global__ void __launch_bounds__(256, 2) gemm_h(
    const __half* __restrict__ Av, const __half* __restrict__ Bv,
    const float* __restrict__ bias, const float* __restrict__ resid,
    float* __restrict__ C, int NT, int Kel, int N) {
    extern __shared__ char smem[];
    uint32_t dataA = (smem_u32(smem) + 1023) & ~1023u;
    int tid = threadIdx.x;
    int wid = tid >> 5, lane = tid & 31;

    int g = blockIdx.x / (16*18);
    int r = blockIdx.x % (16*18);
    int gn = NT - g*18; if (gn > 18) gn = 18;
    int bn = (g*18 + r % gn) * 128;
    int bm = (r / gn) * 128;

    const size_t rowbA = (size_t)Kel * 2;
    const size_t rowbB = (size_t)Kel * 2 * NPH;
    const char* Abase = (const char*)Av + (size_t)bm * rowbA;
    const char* Bbase = (const char*)Bv + (size_t)bn * rowbB;
    const int KC = Kel >> 6;
    const int NC = NPH * KC;
    const int c16 = (tid & 7) * 16;
    const int row0 = tid >> 3;

    auto load_chunk = [&](int j) {
        size_t a_byte, b_byte;
        if (NPH == 2) {
            int phase = (j >= KC) ? 1 : 0;
            int jj = j - phase*KC;
            a_byte = (size_t)jj * 128 + c16;
            b_byte = ((size_t)(phase ? 0 : Kel) + (size_t)jj*64) * 2 + c16;
        } else {
            a_byte = (size_t)j * 128 + c16;
            b_byte = (size_t)j * 128 + c16;
        }
        int s = j % NSTAGE;
        uint32_t sA = dataA + s*STAGE_BYTES;
        uint32_t sB = sA + 16384;
#pragma unroll
        for (int p = 0; p < 4; p++) {
            int row = row0 + p*32;
            uint32_t sw = row*128 + (c16 ^ ((row & 7) << 4));
            cp16(sA + sw, Abase + (size_t)row * rowbA + a_byte);
            cp16(sB + sw, Bbase + (size_t)row * rowbB + b_byte);
        }
        asm volatile("cp.async.commit_group;" ::: "memory");
    };

    float acc[4][4][4];
#pragma unroll
    for (int a = 0; a < 4; a++)
#pragma unroll
        for (int b = 0; b < 4; b++)
#pragma unroll
            for (int c = 0; c < 4; c++) acc[a][b][c] = 0.f;

    const int warp_m = (wid & 1) * 64;
    const int warp_n = (wid >> 1) * 32;

    load_chunk(0);
    load_chunk(1);

    for (int i = 0; i < NC; i++) {
        asm volatile("cp.async.wait_group 1;" ::: "memory");
        __syncthreads();

        if (NPH == 2 && i == KC) {
#pragma unroll
            for (int a = 0; a < 4; a++)
#pragma unroll
                for (int b = 0; b < 4; b++)
#pragma unroll
                    for (int c = 0; c < 4; c++) acc[a][b][c] *= LO_INV;
        }

        uint32_t sA = dataA + (i % NSTAGE)*STAGE_BYTES;
        uint32_t sB = sA + 16384;
#pragma unroll
        for (int ks = 0; ks < 4; ks++) {
            int kb = ks * 32;
            uint32_t af[4][4];
#pragma unroll
            for (int mt = 0; mt < 4; mt++) {
                int rw = warp_m + mt*16 + (lane & 15);
                int cb = kb + ((lane >> 4) << 4);
                ldsm4(af[mt], sA + rw*128 + (cb ^ ((rw & 7) << 4)));
            }
            uint32_t bf[2][4];
#pragma unroll
            for (int nt = 0; nt < 2; nt++) {
                int nr = warp_n + nt*16 + ((lane >> 4) << 3) + (lane & 7);
                int cb = kb + (((lane >> 3) & 1) << 4);
                ldsm4(bf[nt], sB + nr*128 + (cb ^ ((nr & 7) << 4)));
            }
#pragma unroll
            for (int mt = 0; mt < 4; mt++) {
#pragma unroll
                for (int nj = 0; nj < 4; nj++) {
                    const uint32_t* bb = bf[nj >> 1];
                    uint32_t b0 = (nj & 1) ? bb[2] : bb[0];
                    uint32_t b1 = (nj & 1) ? bb[3] : bb[1];
                    mma_f16(acc[mt][nj], af[mt], b0, b1);
                }
            }
        }
        if (i + 2 < NC) load_chunk(i + 2);
        else asm volatile("cp.async.commit_group;" ::: "memory");
    }

    // epilogue
#pragma unroll
    for (int mt = 0; mt < 4; mt++) {
        int row0g = bm + warp_m + mt*16 + (lane >> 2);
#pragma unroll
        for (int nj = 0; nj < 4; nj++) {
            int col = bn + warp_n + nj*8 + (lane & 3)*2;
            float b0 = 0.f, b1 = 0.f;
            if (bias) { b0 = bias[col]; b1 = bias[col+1]; }
            float* p0 = C + (size_t)row0g * N + col;
            float* p1 = C + (size_t)(row0g + 8) * N + col;
            float2 v0 = make_float2(acc[mt][nj][0] + b0, acc[mt][nj][1] + b1);
            float2 v1 = make_float2(acc[mt][nj][2] + b0, acc[mt][nj][3] + b1);
            if (resid) {
                float2 r0 = *(const float2*)(resid + (size_t)row0g * N + col);
                float2 r1 = *(const float2*)(resid + (size_t)(row0g + 8) * N + col);
                v0.x += r0.x; v0.y += r0.y; v1.x += r1.x; v1.y += r1.y;
            }
            *(float2*)p0 = v0;
            *(float2*)p1 = v1;
        }
    }
}

// ------------------------- RoPE (in-place on q,k of qkv) -------------------------
__global__ void rope_kernel(const int* __restrict__ positions, float* __restrict__ qkv) {
    int bs = blockIdx.x;
    int hh = blockIdx.y;
    int i  = threadIdx.x;
    float* base = qkv + (size_t)bs * QKV_DIM + hh * HD;
    float pos = (float)positions[bs];
    float freq = __expf(-(float)i * 0.14391565217f);
    float ang = pos * freq;
    float sn, cs;
    sincosf(ang, &sn, &cs);
    float x1 = base[i];
    float x2 = base[i + 64];
    base[i]      = x1 * cs - x2 * sn;
    base[i + 64] = x2 * cs + x1 * sn;
}

// ------------------------- flash attention v2: 64 q-rows/block, 256 thr ----
// dynamic smem layout (floats):
//   Qs  [64*128]           @ 0
//   KVs [32*128]           @ 8192
//   Ss  [64*33]            @ 12288
//   m/l/alpha [64] each    @ 14400
#define ATT_SMEM ((14400 + 3*64) * 4)

__global__ void __launch_bounds__(256) flash_attn_kernel(
    const float* __restrict__ qkv, __half* __restrict__ ah) {
    extern __shared__ float sm[];
    float* Qs  = sm;                 // [64][128]
    float* KVs = sm + 8192;          // [32][128]
    float* Ss  = sm + 12288;         // [64][33]
    float* m_s = sm + 14400;
    float* l_s = m_s + 64;
    float* alpha_s = l_s + 64;

    int qt = gridDim.x - 1 - blockIdx.x;   // heavy (high-qt) blocks first
    int h  = blockIdx.y;
    int b  = blockIdx.z;
    int kvh = h >> 4;
    int tid = threadIdx.x;
    int r  = tid >> 2;                // query row 0..63
    int qd = tid & 3;                 // dim quarter
    int q0 = qt * 64;

    // load Q tile: 64 rows x 32 float4
    for (int i = tid; i < 64*32; i += 256) {
        int row = i >> 5, c4 = i & 31;
        ((float4*)(Qs + row*HD))[c4] =
            *(const float4*)(qkv + (size_t)(b*SEQ + q0 + row) * QKV_DIM + h*HD + c4*4);
    }
    if (tid < 64) { m_s[tid] = -1e30f; l_s[tid] = 0.f; }
    float acc[32];
#pragma unroll
    for (int i = 0; i < 32; i++) acc[i] = 0.f;
    __syncthreads();

    const float scale = 0.08838834764831845f;
    const int nkt = 2*qt + 2;         // key tiles of 32 covering [0, q0+64)

    for (int kt = 0; kt < nkt; kt++) {
        int k0 = kt * 32;
        // load K tile: 32 rows x 32 float4
        for (int i = tid; i < 32*32; i += 256) {
            int row = i >> 5, c4 = i & 31;
            ((float4*)(KVs + row*HD))[c4] =
                *(const float4*)(qkv + (size_t)(b*SEQ + k0 + row) * QKV_DIM + K_OFF + kvh*HD + c4*4);
        }
        __syncthreads();

        // scores: thread (r, qd) computes keys j0..j0+7 for row r
        int j0 = qd * 8;
        float sc[8];
#pragma unroll
        for (int jj = 0; jj < 8; jj++) sc[jj] = 0.f;
        const float4* q4 = (const float4*)(Qs + r*HD);
#pragma unroll 4
        for (int d4 = 0; d4 < 32; d4++) {
            float4 qv = q4[d4];
#pragma unroll
            for (int jj = 0; jj < 8; jj++) {
                float4 kv = ((const float4*)(KVs + (j0 + jj)*HD))[d4];
                sc[jj] += qv.x*kv.x + qv.y*kv.y + qv.z*kv.z + qv.w*kv.w;
            }
        }
#pragma unroll
        for (int jj = 0; jj < 8; jj++) {
            int kg = k0 + j0 + jj;
            Ss[r*33 + j0 + jj] = (kg <= q0 + r) ? sc[jj] * scale : -1e30f;
        }
        __syncthreads();

        // online softmax per row (one thread per row, 64 rows)
        if (tid < 64) {
            float* srow = Ss + tid*33;
            float mx = m_s[tid];
            float tm = -1e30f;
#pragma unroll 8
            for (int j = 0; j < 32; j++) tm = fmaxf(tm, srow[j]);
            float mn = fmaxf(mx, tm);
            float al = __expf(mx - mn);
            float sum = 0.f;
#pragma unroll 8
            for (int j = 0; j < 32; j++) {
                float p = __expf(srow[j] - mn);
                srow[j] = p;
                sum += p;
            }
            m_s[tid] = mn;
            l_s[tid] = l_s[tid] * al + sum;
            alpha_s[tid] = al;
        }
        // load V tile into same buffer
        for (int i = tid; i < 32*32; i += 256) {
            int row = i >> 5, c4 = i & 31;
            ((float4*)(KVs + row*HD))[c4] =
                *(const float4*)(qkv + (size_t)(b*SEQ + k0 + row) * QKV_DIM + V_OFF + kvh*HD + c4*4);
        }
        __syncthreads();

        // rescale + P@V
        float al = alpha_s[r];
#pragma unroll
        for (int i = 0; i < 32; i++) acc[i] *= al;
        const float* prow = Ss + r*33;
#pragma unroll 4
        for (int j = 0; j < 32; j++) {
            float p = prow[j];
            const float4* v4 = (const float4*)(KVs + j*HD + qd*32);
#pragma unroll
            for (int i4 = 0; i4 < 8; i4++) {
                float4 vv = v4[i4];
                acc[i4*4+0] = fmaf(p, vv.x, acc[i4*4+0]);
                acc[i4*4+1] = fmaf(p, vv.y, acc[i4*4+1]);
                acc[i4*4+2] = fmaf(p, vv.z, acc[i4*4+2]);
                acc[i4*4+3] = fmaf(p, vv.w, acc[i4*4+3]);
            }
        }
        __syncthreads();
    }

    float invl = 1.f / l_s[r];
    uint2* o2 = (uint2*)(ah + (size_t)(b*SEQ + q0 + r) * HID + h*HD + qd*32);
#pragma unroll
    for (int i4 = 0; i4 < 8; i4++) {
        float4 o = make_float4(acc[i4*4+0]*invl, acc[i4*4+1]*invl,
                               acc[i4*4+2]*invl, acc[i4*4+3]*invl);
        o2[i4] = pack4h(o);
    }
}

// ------------------------- SwiGLU -> fp16 single -------------------------
__global__ void swiglu_h_kernel(const float* __restrict__ inter,
                                __half* __restrict__ gh) {
    int t = blockIdx.x * blockDim.x + threadIdx.x;
    if (t >= M_ROWS * (FFN/4)) return;
    int row = t / (FFN/4);
    int f4  = t - row * (FFN/4);
    const float* irow = inter + (size_t)row * (2*FFN);
    float4 a = *(const float4*)(irow + f4*4);
    float4 b = *(const float4*)(irow + FFN + f4*4);
    float4 o;
    o.x = (a.x / (1.f + __expf(-a.x))) * b.x;
    o.y = (a.y / (1.f + __expf(-a.y))) * b.y;
    o.z = (a.z / (1.f + __expf(-a.z))) * b.z;
    o.w = (a.w / (1.f + __expf(-a.w))) * b.w;
    ((uint2*)(gh + (size_t)row * FFN))[f4] = pack4h(o);
}

// ------------------------- launch -------------------------
extern "C" void kernel_launch(void* const* d_in, const int* in_sizes, int n_in,
                              void* d_out, int out_size) {
    const int*   positions = (const int*)d_in[0];
    const float* hs        = (const float*)d_in[1];
    const float* ln1       = (const float*)d_in[2];
    const float* wqkv      = (const float*)d_in[3];
    const float* bqkv      = (const float*)d_in[4];
    const float* wo        = (const float*)d_in[5];
    const float* ln2       = (const float*)d_in[6];
    const float* w14       = (const float*)d_in[7];
    const float* w41       = (const float*)d_in[8];
    float* out = (float*)d_out;

    float *qkv, *attnout, *hidden, *inter;
    __half *wqkvh, *woh, *w14h, *w41h, *xh, *ah, *yh, *gh;
    cudaGetSymbolAddress((void**)&qkv,     g_qkv);
    cudaGetSymbolAddress((void**)&attnout, g_attnout);
    cudaGetSymbolAddress((void**)&hidden,  g_hidden);
    cudaGetSymbolAddress((void**)&inter,   g_inter);
    cudaGetSymbolAddress((void**)&wqkvh,   g_wqkvh);
    cudaGetSymbolAddress((void**)&woh,     g_woh);
    cudaGetSymbolAddress((void**)&w14h,    g_w14h);
    cudaGetSymbolAddress((void**)&w41h,    g_w41h);
    cudaGetSymbolAddress((void**)&xh,      g_xh);
    cudaGetSymbolAddress((void**)&ah,      g_ah);
    cudaGetSymbolAddress((void**)&yh,      g_yh);
    cudaGetSymbolAddress((void**)&gh,      g_gh);

    cudaFuncSetAttribute(gemm_h<2>, cudaFuncAttributeMaxDynamicSharedMemorySize, GEMM_SMEM);
    cudaFuncSetAttribute(gemm_h<1>, cudaFuncAttributeMaxDynamicSharedMemorySize, GEMM_SMEM);
    cudaFuncSetAttribute(flash_attn_kernel, cudaFuncAttributeMaxDynamicSharedMemorySize, ATT_SMEM);

    // weight conversions
    {
        long long n4;
        n4 = (long long)QKV_DIM * HID / 4;
        split_planar_f16<<<(unsigned)((n4+255)/256), 256>>>(wqkv, wqkvh, n4, HID/4);
        n4 = (long long)HID * HID / 4;
        split_planar_f16<<<(unsigned)((n4+255)/256), 256>>>(wo, woh, n4, HID/4);
        n4 = (long long)(2*FFN) * HID / 4;
        round_f16_kernel<<<(unsigned)((n4+255)/256), 256>>>(w14, w14h, n4);
        n4 = (long long)HID * FFN / 4;
        round_f16_kernel<<<(unsigned)((n4+255)/256), 256>>>(w41, w41h, n4);
    }

    // 1) xh = f16(rmsnorm(hs) * ln1)
    fused_norm_kernel<<<M_ROWS, 256>>>(nullptr, hs, ln1, nullptr, xh);

    // 2) qkv = x @ wqkv^T + bqkv   (2-phase exact weights)
    gemm_h<2><<<16*36, 256, GEMM_SMEM>>>(xh, wqkvh, bqkv, nullptr, qkv, 36, HID, QKV_DIM);

    // 3) rope on q,k
    rope_kernel<<<dim3(M_ROWS, NH + NKV), 64>>>(positions, qkv);

    // 4) attention -> ah (fp16 ctx), 64 q-rows/block
    flash_attn_kernel<<<dim3(SEQ/64, NH, BATCH), 256, ATT_SMEM>>>(qkv, ah);

    // 5) attn_out = ctx @ wo^T   (2-phase exact weights)
    gemm_h<2><<<16*32, 256, GEMM_SMEM>>>(ah, woh, nullptr, nullptr, attnout, 32, HID, HID);

    // 6) hidden = hs + attn_out ; yh = f16(rmsnorm(hidden) * ln2)
    fused_norm_kernel<<<M_ROWS, 256>>>(hs, attnout, ln2, hidden, yh);

    // 7) inter = y @ w14^T   (1-phase fp16 weights)
    gemm_h<1><<<16*214, 256, GEMM_SMEM>>>(yh, w14h, nullptr, nullptr, inter, 214, HID, 2*FFN);

    // 8) gh = f16(silu(a)*b)
    swiglu_h_kernel<<<(M_ROWS*(FFN/4) + 255)/256, 256>>>(inter, gh);

    // 9) out = hidden + gated @ w41^T   (1-phase fp16 weights, residual fused)
    gemm_h<1><<<16*32, 256, GEMM_SMEM>>>(gh, w41h, nullptr, hidden, out, 32, FFN, HID);
}

// round 13
// speedup vs baseline: 1.9042x; 1.9042x over previous
#include <cuda_runtime.h>
#include <cuda_fp16.h>
#include <math.h>
#include <stdint.h>

#define BATCH 2
#define SEQ 1024
#define HID 4096
#define NH 32
#define NKV 2
#define HD 128
#define FFN 13696
#define QKV_DIM ((NH + 2*NKV)*HD)   // 4608
#define M_ROWS (BATCH*SEQ)          // 2048
#define EPSV 1e-5f
#define V_OFF ((NH+NKV)*HD)         // 4352
#define K_OFF (NH*HD)               // 4096
#define K2H (2*HID)
#define LO_SCALE 4096.0f            // 2^12
#define LO_INV   2.44140625e-4f     // 2^-12

// ------------------------- scratch (device globals) -------------------------
__device__ float g_qkv[(size_t)M_ROWS * QKV_DIM];
__device__ float g_attnout[(size_t)M_ROWS * HID];
__device__ float g_hidden[(size_t)M_ROWS * HID];
// fp16 weights: QKV/O planar split [hi | lo*2^12]; FFN single-plane fp16
// w14 rows PERMUTED: orig row f -> 2f, orig row FFN+f -> 2f+1 (SwiGLU pairing)
__device__ __half g_wqkvh[(size_t)QKV_DIM * K2H];
__device__ __half g_woh[(size_t)HID * K2H];
__device__ __half g_w14h[(size_t)(2*FFN) * HID];
__device__ __half g_w41h[(size_t)HID * FFN];
// fp16 single activations
__device__ __half g_xh[(size_t)M_ROWS * HID];
__device__ __half g_ah[(size_t)M_ROWS * HID];
__device__ __half g_yh[(size_t)M_ROWS * HID];
__device__ __half g_gh[(size_t)M_ROWS * FFN];

// ------------------------- PTX helpers -------------------------
__device__ __forceinline__ uint32_t smem_u32(const void* p) {
    uint32_t a;
    asm("{ .reg .u64 t; cvta.to.shared.u64 t, %1; cvt.u32.u64 %0, t; }" : "=r"(a) : "l"(p));
    return a;
}
__device__ __forceinline__ void cp16(uint32_t s, const void* g) {
    asm volatile("cp.async.cg.shared.global [%0], [%1], 16;" :: "r"(s), "l"(g));
}
__device__ __forceinline__ void ldsm4(uint32_t* r, uint32_t addr) {
    asm volatile("ldmatrix.sync.aligned.m8n8.x4.shared.b16 {%0,%1,%2,%3}, [%4];"
                 : "=r"(r[0]), "=r"(r[1]), "=r"(r[2]), "=r"(r[3]) : "r"(addr));
}
__device__ __forceinline__ void mma_f16(float* c, const uint32_t* a, uint32_t b0, uint32_t b1) {
    asm volatile(
        "mma.sync.aligned.m16n8k16.row.col.f32.f16.f16.f32 "
        "{%0,%1,%2,%3}, {%4,%5,%6,%7}, {%8,%9}, {%0,%1,%2,%3};"
        : "+f"(c[0]), "+f"(c[1]), "+f"(c[2]), "+f"(c[3])
        : "r"(a[0]), "r"(a[1]), "r"(a[2]), "r"(a[3]), "r"(b0), "r"(b1));
}

// ------------------------- misc helpers -------------------------
__device__ __forceinline__ float warp_sum(float v) {
#pragma unroll
    for (int o = 16; o > 0; o >>= 1) v += __shfl_xor_sync(0xffffffffu, v, o);
    return v;
}
__device__ __forceinline__ void split4h_scaled(float4 v, uint2& hi, uint2& lo) {
    union { uint2 u; __half h[4]; } H, L;
    float f[4] = {v.x, v.y, v.z, v.w};
#pragma unroll
    for (int k = 0; k < 4; k++) {
        __half h = __float2half_rn(f[k]);
        H.h[k] = h;
        L.h[k] = __float2half_rn((f[k] - __half2float(h)) * LO_SCALE);
    }
    hi = H.u; lo = L.u;
}
__device__ __forceinline__ uint2 pack4h(float4 v) {
    union { uint2 u; __half h[4]; } H;
    H.h[0] = __float2half_rn(v.x); H.h[1] = __float2half_rn(v.y);
    H.h[2] = __float2half_rn(v.z); H.h[3] = __float2half_rn(v.w);
    return H.u;
}

// ------------------------- weight conversion kernels -------------------------
__global__ void split_planar_f16(const float* __restrict__ in,
                                 __half* __restrict__ out,
                                 long long n4, int kq) {
    long long i = (long long)blockIdx.x * blockDim.x + threadIdx.x;
    if (i >= n4) return;
    float4 v = ((const float4*)in)[i];
    uint2 hi, lo;
    split4h_scaled(v, hi, lo);
    long long n = i / kq;
    long long hidx = i + n * kq;
    ((uint2*)out)[hidx] = hi;
    ((uint2*)out)[hidx + kq] = lo;
}
__global__ void round_f16_kernel(const float* __restrict__ in,
                                 __half* __restrict__ out, long long n4) {
    long long i = (long long)blockIdx.x * blockDim.x + threadIdx.x;
    if (i >= n4) return;
    ((uint2*)out)[i] = pack4h(((const float4*)in)[i]);
}
// w14 conversion with SwiGLU row interleave: orig row f -> 2f, FFN+f -> 2f+1
__global__ void round_f16_interleave_kernel(const float* __restrict__ in,
                                            __half* __restrict__ out,
                                            long long n4, int kq) {
    long long i = (long long)blockIdx.x * blockDim.x + threadIdx.x;
    if (i >= n4) return;
    long long n = i / kq;
    long long k4 = i - n * kq;
    long long nn = (n < FFN) ? 2*n : 2*(n - FFN) + 1;
    ((uint2*)out)[nn * kq + k4] = pack4h(((const float4*)in)[i]);
}

// ------------------------- fused (add+)rmsnorm -> fp16 single -------------------------
__global__ void __launch_bounds__(256) fused_norm_kernel(
    const float* __restrict__ res, const float* __restrict__ x,
    const float* __restrict__ w, float* __restrict__ hid_out,
    __half* __restrict__ yh) {
    __shared__ __align__(16) float buf[HID];
    __shared__ float red[8];
    int row = blockIdx.x;
    size_t base = (size_t)row * HID;
    const float4* x4 = (const float4*)(x + base);
    const float4* r4 = res ? (const float4*)(res + base) : nullptr;
    float4* b4 = (float4*)buf;

    float ss = 0.f;
    for (int i = threadIdx.x; i < HID/4; i += 256) {
        float4 v = x4[i];
        if (r4) { float4 rr = r4[i]; v.x += rr.x; v.y += rr.y; v.z += rr.z; v.w += rr.w; }
        b4[i] = v;
        ss += v.x*v.x + v.y*v.y + v.z*v.z + v.w*v.w;
    }
    ss = warp_sum(ss);
    if ((threadIdx.x & 31) == 0) red[threadIdx.x >> 5] = ss;
    __syncthreads();
    float tot = 0.f;
#pragma unroll
    for (int i = 0; i < 8; i++) tot += red[i];
    float inv = rsqrtf(tot / (float)HID + EPSV);

    float4* h4 = hid_out ? (float4*)(hid_out + base) : nullptr;
    const float4* w4 = (const float4*)w;
    uint2* y2 = (uint2*)(yh + base);
    for (int i = threadIdx.x; i < HID/4; i += 256) {
        float4 v = b4[i];
        if (h4) h4[i] = v;
        float4 ww = w4[i];
        float4 o;
        o.x = v.x * inv * ww.x; o.y = v.y * inv * ww.y;
        o.z = v.z * inv * ww.z; o.w = v.w * inv * ww.w;
        y2[i] = pack4h(o);
    }
}

// ------------------------- fp16 HMMA GEMM (R9/R11 config) -------------------------
// NPH=2: B planar [hi | lo*2^12]; phase 0 = lo, fold acc *= 2^-12, phase 1 = hi.
// NPH=1: B single fp16 plane.
// SWI: epilogue computes silu(a)*b over column pairs (requires interleaved B rows),
//      writes __half to C viewed as [M, N/2]; bias/resid ignored.
#define NSTAGE 3
#define STAGE_BYTES 32768
#define GEMM_SMEM (NSTAGE * STAGE_BYTES + 1024)

template<int NPH, bool SWI>
__global__ void __launch_bounds__(256, 2) gemm_h(
    const __half* __restrict__ Av, const __half* __restrict__ Bv,
    const float* __restrict__ bias, const float* __restrict__ resid,
    void* __restrict__ Cv, int NT, int Kel, int N) {
    extern __shared__ char smem[];
    uint32_t dataA = (smem_u32(smem) + 1023) & ~1023u;
    int tid = threadIdx.x;
    int wid = tid >> 5, lane = tid & 31;

    int g = blockIdx.x / (16*18);
    int r = blockIdx.x % (16*18);
    int gn = NT - g*18; if (gn > 18) gn = 18;
    int bn = (g*18 + r % gn) * 128;
    int bm = (r / gn) * 128;

    const size_t rowbA = (size_t)Kel * 2;
    const size_t rowbB = (size_t)Kel * 2 * NPH;
    const char* Abase = (const char*)Av + (size_t)bm * rowbA;
    const char* Bbase = (const char*)Bv + (size_t)bn * rowbB;
    const int KC = Kel >> 6;
    const int NC = NPH * KC;
    const int c16 = (tid & 7) * 16;
    const int row0 = tid >> 3;

    auto load_chunk = [&](int j) {
        size_t a_byte, b_byte;
        if (NPH == 2) {
            int phase = (j >= KC) ? 1 : 0;
            int jj = j - phase*KC;
            a_byte = (size_t)jj * 128 + c16;
            b_byte = ((size_t)(phase ? 0 : Kel) + (size_t)jj*64) * 2 + c16;
        } else {
            a_byte = (size_t)j * 128 + c16;
            b_byte = (size_t)j * 128 + c16;
        }
        int s = j % NSTAGE;
        uint32_t sA = dataA + s*STAGE_BYTES;
        uint32_t sB = sA + 16384;
#pragma unroll
        for (int p = 0; p < 4; p++) {
            int row = row0 + p*32;
            uint32_t sw = row*128 + (c16 ^ ((row & 7) << 4));
            cp16(sA + sw, Abase + (size_t)row * rowbA + a_byte);
            cp16(sB + sw, Bbase + (size_t)row * rowbB + b_byte);
        }
        asm volatile("cp.async.commit_group;" ::: "memory");
    };

    float acc[4][4][4];
#pragma unroll
    for (int a = 0; a < 4; a++)
#pragma unroll
        for (int b = 0; b < 4; b++)
#pragma unroll
            for (int c = 0; c < 4; c++) acc[a][b][c] = 0.f;

    const int warp_m = (wid & 1) * 64;
    const int warp_n = (wid >> 1) * 32;

    load_chunk(0);
    load_chunk(1);

    for (int i = 0; i < NC; i++) {
        asm volatile("cp.async.wait_group 1;" ::: "memory");
        __syncthreads();

        if (NPH == 2 && i == KC) {
#pragma unroll
            for (int a = 0; a < 4; a++)
#pragma unroll
                for (int b = 0; b < 4; b++)
#pragma unroll
                    for (int c = 0; c < 4; c++) acc[a][b][c] *= LO_INV;
        }

        uint32_t sA = dataA + (i % NSTAGE)*STAGE_BYTES;
        uint32_t sB = sA + 16384;
#pragma unroll
        for (int ks = 0; ks < 4; ks++) {
            int kb = ks * 32;
            uint32_t af[4][4];
#pragma unroll
            for (int mt = 0; mt < 4; mt++) {
                int rw = warp_m + mt*16 + (lane & 15);
                int cb = kb + ((lane >> 4) << 4);
                ldsm4(af[mt], sA + rw*128 + (cb ^ ((rw & 7) << 4)));
            }
            uint32_t bf[2][4];
#pragma unroll
            for (int nt = 0; nt < 2; nt++) {
                int nr = warp_n + nt*16 + ((lane >> 4) << 3) + (lane & 7);
                int cb = kb + (((lane >> 3) & 1) << 4);
                ldsm4(bf[nt], sB + nr*128 + (cb ^ ((nr & 7) << 4)));
            }
#pragma unroll
            for (int mt = 0; mt < 4; mt++) {
#pragma unroll
                for (int nj = 0; nj < 4; nj++) {
                    const uint32_t* bb = bf[nj >> 1];
                    uint32_t b0 = (nj & 1) ? bb[2] : bb[0];
                    uint32_t b1 = (nj & 1) ? bb[3] : bb[1];
                    mma_f16(acc[mt][nj], af[mt], b0, b1);
                }
            }
        }
        if (i + 2 < NC) load_chunk(i + 2);
        else asm volatile("cp.async.commit_group;" ::: "memory");
    }

    // epilogue
#pragma unroll
    for (int mt = 0; mt < 4; mt++) {
        int row0g = bm + warp_m + mt*16 + (lane >> 2);
#pragma unroll
        for (int nj = 0; nj < 4; nj++) {
            int col = bn + warp_n + nj*8 + (lane & 3)*2;
            if (SWI) {
                // acc pair (col, col+1) = (a_f, b_f) with f = col/2 (interleaved B rows)
                __half* G = (__half*)Cv;
                int Nh = N >> 1;
                float a0 = acc[mt][nj][0], b0v = acc[mt][nj][1];
                float a1 = acc[mt][nj][2], b1v = acc[mt][nj][3];
                float s0 = (a0 / (1.f + __expf(-a0))) * b0v;
                float s1 = (a1 / (1.f + __expf(-a1))) * b1v;
                G[(size_t)row0g * Nh + (col >> 1)] = __float2half_rn(s0);
                G[(size_t)(row0g + 8) * Nh + (col >> 1)] = __float2half_rn(s1);
            } else {
                float* C = (float*)Cv;
                float b0 = 0.f, b1 = 0.f;
                if (bias) { b0 = bias[col]; b1 = bias[col+1]; }
                float* p0 = C + (size_t)row0g * N + col;
                float* p1 = C + (size_t)(row0g + 8) * N + col;
                float2 v0 = make_float2(acc[mt][nj][0] + b0, acc[mt][nj][1] + b1);
                float2 v1 = make_float2(acc[mt][nj][2] + b0, acc[mt][nj][3] + b1);
                if (resid) {
                    float2 r0 = *(const float2*)(resid + (size_t)row0g * N + col);
                    float2 r1 = *(const float2*)(resid + (size_t)(row0g + 8) * N + col);
                    v0.x += r0.x; v0.y += r0.y; v1.x += r1.x; v1.y += r1.y;
                }
                *(float2*)p0 = v0;
                *(float2*)p1 = v1;
            }
        }
    }
}

// ------------------------- RoPE (in-place on q,k of qkv) -------------------------
__global__ void rope_kernel(const int* __restrict__ positions, float* __restrict__ qkv) {
    int bs = blockIdx.x;
    int hh = blockIdx.y;
    int i  = threadIdx.x;
    float* base = qkv + (size_t)bs * QKV_DIM + hh * HD;
    float pos = (float)positions[bs];
    float freq = __expf(-(float)i * 0.14391565217f);
    float ang = pos * freq;
    float sn, cs;
    sincosf(ang, &sn, &cs);
    float x1 = base[i];
    float x2 = base[i + 64];
    base[i]      = x1 * cs - x2 * sn;
    base[i + 64] = x2 * cs + x1 * sn;
}

// ------------------------- flash attention (R11/v1: 32 q-rows, 128 thr) ----
__global__ void __launch_bounds__(128) flash_attn_kernel(
    const float* __restrict__ qkv, __half* __restrict__ ah) {
    __shared__ __align__(16) float Qs[32][HD];
    __shared__ __align__(16) float KVs[32][HD];
    __shared__ float Ss[32][33];
    __shared__ float m_s[32], l_s[32], alpha_s[32];

    int qt = blockIdx.x;
    int h  = blockIdx.y;
    int b  = blockIdx.z;
    int kvh = h >> 4;
    int tid = threadIdx.x;
    int r  = tid >> 2;
    int qd = tid & 3;
    int q0 = qt * 32;

    for (int i = tid; i < 32*32; i += 128) {
        int row = i >> 5, c4 = i & 31;
        ((float4*)Qs[row])[c4] =
            *(const float4*)(qkv + (size_t)(b*SEQ + q0 + row) * QKV_DIM + h*HD + c4*4);
    }
    if (tid < 32) { m_s[tid] = -1e30f; l_s[tid] = 0.f; }
    float acc[32];
#pragma unroll
    for (int i = 0; i < 32; i++) acc[i] = 0.f;
    __syncthreads();

    const float scale = 0.08838834764831845f;

    for (int kt = 0; kt <= qt; kt++) {
        int k0 = kt * 32;
        for (int i = tid; i < 32*32; i += 128) {
            int row = i >> 5, c4 = i & 31;
            ((float4*)KVs[row])[c4] =
                *(const float4*)(qkv + (size_t)(b*SEQ + k0 + row) * QKV_DIM + K_OFF + kvh*HD + c4*4);
        }
        __syncthreads();

        int j0 = qd * 8;
        float sc[8];
#pragma unroll
        for (int jj = 0; jj < 8; jj++) sc[jj] = 0.f;
        const float4* q4 = (const float4*)Qs[r];
#pragma unroll 4
        for (int d4 = 0; d4 < 32; d4++) {
            float4 qv = q4[d4];
#pragma unroll
            for (int jj = 0; jj < 8; jj++) {
                float4 kv = ((const float4*)KVs[j0 + jj])[d4];
                sc[jj] += qv.x*kv.x + qv.y*kv.y + qv.z*kv.z + qv.w*kv.w;
            }
        }
#pragma unroll
        for (int jj = 0; jj < 8; jj++) {
            int kg = k0 + j0 + jj;
            Ss[r][j0 + jj] = (kg <= q0 + r) ? sc[jj] * scale : -1e30f;
        }
        __syncthreads();

        if (tid < 32) {
            float mx = m_s[tid];
            float tm = -1e30f;
#pragma unroll 8
            for (int j = 0; j < 32; j++) tm = fmaxf(tm, Ss[tid][j]);
            float mn = fmaxf(mx, tm);
            float al = __expf(mx - mn);
            float sum = 0.f;
#pragma unroll 8
            for (int j = 0; j < 32; j++) {
                float p = __expf(Ss[tid][j] - mn);
                Ss[tid][j] = p;
                sum += p;
            }
            m_s[tid] = mn;
            l_s[tid] = l_s[tid] * al + sum;
            alpha_s[tid] = al;
        }
        for (int i = tid; i < 32*32; i += 128) {
            int row = i >> 5, c4 = i & 31;
            ((float4*)KVs[row])[c4] =
                *(const float4*)(qkv + (size_t)(b*SEQ + k0 + row) * QKV_DIM + V_OFF + kvh*HD + c4*4);
        }
        __syncthreads();

        float al = alpha_s[r];
#pragma unroll
        for (int i = 0; i < 32; i++) acc[i] *= al;
#pragma unroll 4
        for (int j = 0; j < 32; j++) {
            float p = Ss[r][j];
            const float4* v4 = (const float4*)&KVs[j][qd*32];
#pragma unroll
            for (int i4 = 0; i4 < 8; i4++) {
                float4 vv = v4[i4];
                acc[i4*4+0] = fmaf(p, vv.x, acc[i4*4+0]);
                acc[i4*4+1] = fmaf(p, vv.y, acc[i4*4+1]);
                acc[i4*4+2] = fmaf(p, vv.z, acc[i4*4+2]);
                acc[i4*4+3] = fmaf(p, vv.w, acc[i4*4+3]);
            }
        }
        __syncthreads();
    }

    float invl = 1.f / l_s[r];
    uint2* o2 = (uint2*)(ah + (size_t)(b*SEQ + q0 + r) * HID + h*HD + qd*32);
#pragma unroll
    for (int i4 = 0; i4 < 8; i4++) {
        float4 o = make_float4(acc[i4*4+0]*invl, acc[i4*4+1]*invl,
                               acc[i4*4+2]*invl, acc[i4*4+3]*invl);
        o2[i4] = pack4h(o);
    }
}

// ------------------------- launch -------------------------
extern "C" void kernel_launch(void* const* d_in, const int* in_sizes, int n_in,
                              void* d_out, int out_size) {
    const int*   positions = (const int*)d_in[0];
    const float* hs        = (const float*)d_in[1];
    const float* ln1       = (const float*)d_in[2];
    const float* wqkv      = (const float*)d_in[3];
    const float* bqkv      = (const float*)d_in[4];
    const float* wo        = (const float*)d_in[5];
    const float* ln2       = (const float*)d_in[6];
    const float* w14       = (const float*)d_in[7];
    const float* w41       = (const float*)d_in[8];
    float* out = (float*)d_out;

    float *qkv, *attnout, *hidden;
    __half *wqkvh, *woh, *w14h, *w41h, *xh, *ah, *yh, *gh;
    cudaGetSymbolAddress((void**)&qkv,     g_qkv);
    cudaGetSymbolAddress((void**)&attnout, g_attnout);
    cudaGetSymbolAddress((void**)&hidden,  g_hidden);
    cudaGetSymbolAddress((void**)&wqkvh,   g_wqkvh);
    cudaGetSymbolAddress((void**)&woh,     g_woh);
    cudaGetSymbolAddress((void**)&w14h,    g_w14h);
    cudaGetSymbolAddress((void**)&w41h,    g_w41h);
    cudaGetSymbolAddress((void**)&xh,      g_xh);
    cudaGetSymbolAddress((void**)&ah,      g_ah);
    cudaGetSymbolAddress((void**)&yh,      g_yh);
    cudaGetSymbolAddress((void**)&gh,      g_gh);

    cudaFuncSetAttribute((const void*)&gemm_h<2,false>, cudaFuncAttributeMaxDynamicSharedMemorySize, GEMM_SMEM);
    cudaFuncSetAttribute((const void*)&gemm_h<1,false>, cudaFuncAttributeMaxDynamicSharedMemorySize, GEMM_SMEM);
    cudaFuncSetAttribute((const void*)&gemm_h<1,true>,  cudaFuncAttributeMaxDynamicSharedMemorySize, GEMM_SMEM);

    // weight conversions
    {
        long long n4;
        n4 = (long long)QKV_DIM * HID / 4;
        split_planar_f16<<<(unsigned)((n4+255)/256), 256>>>(wqkv, wqkvh, n4, HID/4);
        n4 = (long long)HID * HID / 4;
        split_planar_f16<<<(unsigned)((n4+255)/256), 256>>>(wo, woh, n4, HID/4);
        n4 = (long long)(2*FFN) * HID / 4;
        round_f16_interleave_kernel<<<(unsigned)((n4+255)/256), 256>>>(w14, w14h, n4, HID/4);
        n4 = (long long)HID * FFN / 4;
        round_f16_kernel<<<(unsigned)((n4+255)/256), 256>>>(w41, w41h, n4);
    }

    // 1) xh = f16(rmsnorm(hs) * ln1)
    fused_norm_kernel<<<M_ROWS, 256>>>(nullptr, hs, ln1, nullptr, xh);

    // 2) qkv = x @ wqkv^T + bqkv   (2-phase exact weights)
    gemm_h<2,false><<<16*36, 256, GEMM_SMEM>>>(xh, wqkvh, bqkv, nullptr, qkv, 36, HID, QKV_DIM);

    // 3) rope on q,k
    rope_kernel<<<dim3(M_ROWS, NH + NKV), 64>>>(positions, qkv);

    // 4) attention -> ah (fp16 ctx), proven v1 kernel
    flash_attn_kernel<<<dim3(SEQ/32, NH, BATCH), 128>>>(qkv, ah);

    // 5) attn_out = ctx @ wo^T   (2-phase exact weights)
    gemm_h<2,false><<<16*32, 256, GEMM_SMEM>>>(ah, woh, nullptr, nullptr, attnout, 32, HID, HID);

    // 6) hidden = hs + attn_out ; yh = f16(rmsnorm(hidden) * ln2)
    fused_norm_kernel<<<M_ROWS, 256>>>(hs, attnout, ln2, hidden, yh);

    // 7) gh = f16(silu(a)*b) fused into FFN-up GEMM (interleaved w14 rows)
    gemm_h<1,true><<<16*214, 256, GEMM_SMEM>>>(yh, w14h, nullptr, nullptr, gh, 214, HID, 2*FFN);

    // 8) out = hidden + gated @ w41^T   (1-phase fp16 weights, residual fused)
    gemm_h<1,false><<<16*32, 256, GEMM_SMEM>>>(gh, w41h, nullptr, hidden, out, 32, FFN, HID);
}

// round 14
// speedup vs baseline: 2.0183x; 1.0599x over previous
#include <cuda_runtime.h>
#include <cuda_fp16.h>
#include <math.h>
#include <stdint.h>

#define BATCH 2
#define SEQ 1024
#define HID 4096
#define NH 32
#define NKV 2
#define HD 128
#define FFN 13696
#define QKV_DIM ((NH + 2*NKV)*HD)   // 4608
#define M_ROWS (BATCH*SEQ)          // 2048
#define EPSV 1e-5f
#define V_OFF ((NH+NKV)*HD)         // 4352
#define K_OFF (NH*HD)               // 4096

// ------------------------- scratch (device globals) -------------------------
__device__ float g_qkv[(size_t)M_ROWS * QKV_DIM];
__device__ float g_attnout[(size_t)M_ROWS * HID];
__device__ float g_hidden[(size_t)M_ROWS * HID];
// fp16 weights (single plane). w14 rows PERMUTED: f -> 2f, FFN+f -> 2f+1.
__device__ __half g_wqkvh[(size_t)QKV_DIM * HID];
__device__ __half g_woh[(size_t)HID * HID];
__device__ __half g_w14h[(size_t)(2*FFN) * HID];
__device__ __half g_w41h[(size_t)HID * FFN];
// fp16 single activations
__device__ __half g_xh[(size_t)M_ROWS * HID];
__device__ __half g_ah[(size_t)M_ROWS * HID];
__device__ __half g_yh[(size_t)M_ROWS * HID];
__device__ __half g_gh[(size_t)M_ROWS * FFN];

// ------------------------- PTX helpers -------------------------
__device__ __forceinline__ uint32_t smem_u32(const void* p) {
    uint32_t a;
    asm("{ .reg .u64 t; cvta.to.shared.u64 t, %1; cvt.u32.u64 %0, t; }" : "=r"(a) : "l"(p));
    return a;
}
__device__ __forceinline__ void cp16(uint32_t s, const void* g) {
    asm volatile("cp.async.cg.shared.global [%0], [%1], 16;" :: "r"(s), "l"(g));
}
__device__ __forceinline__ void ldsm4(uint32_t* r, uint32_t addr) {
    asm volatile("ldmatrix.sync.aligned.m8n8.x4.shared.b16 {%0,%1,%2,%3}, [%4];"
                 : "=r"(r[0]), "=r"(r[1]), "=r"(r[2]), "=r"(r[3]) : "r"(addr));
}
__device__ __forceinline__ void mma_f16(float* c, const uint32_t* a, uint32_t b0, uint32_t b1) {
    asm volatile(
        "mma.sync.aligned.m16n8k16.row.col.f32.f16.f16.f32 "
        "{%0,%1,%2,%3}, {%4,%5,%6,%7}, {%8,%9}, {%0,%1,%2,%3};"
        : "+f"(c[0]), "+f"(c[1]), "+f"(c[2]), "+f"(c[3])
        : "r"(a[0]), "r"(a[1]), "r"(a[2]), "r"(a[3]), "r"(b0), "r"(b1));
}

// ------------------------- misc helpers -------------------------
__device__ __forceinline__ float warp_sum(float v) {
#pragma unroll
    for (int o = 16; o > 0; o >>= 1) v += __shfl_xor_sync(0xffffffffu, v, o);
    return v;
}
__device__ __forceinline__ uint2 pack4h(float4 v) {
    union { uint2 u; __half h[4]; } H;
    H.h[0] = __float2half_rn(v.x); H.h[1] = __float2half_rn(v.y);
    H.h[2] = __float2half_rn(v.z); H.h[3] = __float2half_rn(v.w);
    return H.u;
}

// ------------------------- weight conversion kernels -------------------------
__global__ void round_f16_kernel(const float* __restrict__ in,
                                 __half* __restrict__ out, long long n4) {
    long long i = (long long)blockIdx.x * blockDim.x + threadIdx.x;
    if (i >= n4) return;
    ((uint2*)out)[i] = pack4h(((const float4*)in)[i]);
}
// w14 conversion with SwiGLU row interleave: orig row f -> 2f, FFN+f -> 2f+1
__global__ void round_f16_interleave_kernel(const float* __restrict__ in,
                                            __half* __restrict__ out,
                                            long long n4, int kq) {
    long long i = (long long)blockIdx.x * blockDim.x + threadIdx.x;
    if (i >= n4) return;
    long long n = i / kq;
    long long k4 = i - n * kq;
    long long nn = (n < FFN) ? 2*n : 2*(n - FFN) + 1;
    ((uint2*)out)[nn * kq + k4] = pack4h(((const float4*)in)[i]);
}

// ------------------------- fused (add+)rmsnorm -> fp16 single -------------------------
__global__ void __launch_bounds__(256) fused_norm_kernel(
    const float* __restrict__ res, const float* __restrict__ x,
    const float* __restrict__ w, float* __restrict__ hid_out,
    __half* __restrict__ yh) {
    __shared__ __align__(16) float buf[HID];
    __shared__ float red[8];
    int row = blockIdx.x;
    size_t base = (size_t)row * HID;
    const float4* x4 = (const float4*)(x + base);
    const float4* r4 = res ? (const float4*)(res + base) : nullptr;
    float4* b4 = (float4*)buf;

    float ss = 0.f;
    for (int i = threadIdx.x; i < HID/4; i += 256) {
        float4 v = x4[i];
        if (r4) { float4 rr = r4[i]; v.x += rr.x; v.y += rr.y; v.z += rr.z; v.w += rr.w; }
        b4[i] = v;
        ss += v.x*v.x + v.y*v.y + v.z*v.z + v.w*v.w;
    }
    ss = warp_sum(ss);
    if ((threadIdx.x & 31) == 0) red[threadIdx.x >> 5] = ss;
    __syncthreads();
    float tot = 0.f;
#pragma unroll
    for (int i = 0; i < 8; i++) tot += red[i];
    float inv = rsqrtf(tot / (float)HID + EPSV);

    float4* h4 = hid_out ? (float4*)(hid_out + base) : nullptr;
    const float4* w4 = (const float4*)w;
    uint2* y2 = (uint2*)(yh + base);
    for (int i = threadIdx.x; i < HID/4; i += 256) {
        float4 v = b4[i];
        if (h4) h4[i] = v;
        float4 ww = w4[i];
        float4 o;
        o.x = v.x * inv * ww.x; o.y = v.y * inv * ww.y;
        o.z = v.z * inv * ww.z; o.w = v.w * inv * ww.w;
        y2[i] = pack4h(o);
    }
}

// ------------------------- fp16 1-phase HMMA GEMM -------------------------
// C[M,N] = A(fp16)[M,K] * B(fp16)[N,K]^T (+bias)(+resid).
// SWI: epilogue computes silu(a)*b over column pairs (interleaved B rows),
//      stages tile in smem, coalesced uint4 stores to __half C [M, N/2].
// Tile 128x128, chunk 64, 256 thr = 8 warps (2m x 4n), 3-stage cp.async, 2 CTA/SM.
#define NSTAGE 3
#define STAGE_BYTES 32768
#define GEMM_SMEM (NSTAGE * STAGE_BYTES + 1024)
#define SWI_STRIDE 72   // halves per staged row (bank-conflict padding)

template<bool SWI>
__global__ void __launch_bounds__(256, 2) gemm_h(
    const __half* __restrict__ Av, const __half* __restrict__ Bv,
    const float* __restrict__ bias, const float* __restrict__ resid,
    void* __restrict__ Cv, int NT, int Kel, int N) {
    extern __shared__ char smem[];
    uint32_t dataA = (smem_u32(smem) + 1023) & ~1023u;
    int tid = threadIdx.x;
    int wid = tid >> 5, lane = tid & 31;

    int g = blockIdx.x / (16*18);
    int r = blockIdx.x % (16*18);
    int gn = NT - g*18; if (gn > 18) gn = 18;
    int bn = (g*18 + r % gn) * 128;
    int bm = (r / gn) * 128;

    const size_t rowb = (size_t)Kel * 2;
    const char* Abase = (const char*)Av + (size_t)bm * rowb;
    const char* Bbase = (const char*)Bv + (size_t)bn * rowb;
    const int NC = Kel >> 6;
    const int c16 = (tid & 7) * 16;
    const int row0 = tid >> 3;

    auto load_chunk = [&](int j) {
        size_t off = (size_t)j * 128 + c16;
        int s = j % NSTAGE;
        uint32_t sA = dataA + s*STAGE_BYTES;
        uint32_t sB = sA + 16384;
#pragma unroll
        for (int p = 0; p < 4; p++) {
            int row = row0 + p*32;
            uint32_t sw = row*128 + (c16 ^ ((row & 7) << 4));
            cp16(sA + sw, Abase + (size_t)row * rowb + off);
            cp16(sB + sw, Bbase + (size_t)row * rowb + off);
        }
        asm volatile("cp.async.commit_group;" ::: "memory");
    };

    float acc[4][4][4];
#pragma unroll
    for (int a = 0; a < 4; a++)
#pragma unroll
        for (int b = 0; b < 4; b++)
#pragma unroll
            for (int c = 0; c < 4; c++) acc[a][b][c] = 0.f;

    const int warp_m = (wid & 1) * 64;
    const int warp_n = (wid >> 1) * 32;

    load_chunk(0);
    load_chunk(1);

    for (int i = 0; i < NC; i++) {
        asm volatile("cp.async.wait_group 1;" ::: "memory");
        __syncthreads();

        uint32_t sA = dataA + (i % NSTAGE)*STAGE_BYTES;
        uint32_t sB = sA + 16384;
#pragma unroll
        for (int ks = 0; ks < 4; ks++) {
            int kb = ks * 32;
            uint32_t af[4][4];
#pragma unroll
            for (int mt = 0; mt < 4; mt++) {
                int rw = warp_m + mt*16 + (lane & 15);
                int cb = kb + ((lane >> 4) << 4);
                ldsm4(af[mt], sA + rw*128 + (cb ^ ((rw & 7) << 4)));
            }
            uint32_t bf[2][4];
#pragma unroll
            for (int nt = 0; nt < 2; nt++) {
                int nr = warp_n + nt*16 + ((lane >> 4) << 3) + (lane & 7);
                int cb = kb + (((lane >> 3) & 1) << 4);
                ldsm4(bf[nt], sB + nr*128 + (cb ^ ((nr & 7) << 4)));
            }
#pragma unroll
            for (int mt = 0; mt < 4; mt++) {
#pragma unroll
                for (int nj = 0; nj < 4; nj++) {
                    const uint32_t* bb = bf[nj >> 1];
                    uint32_t b0 = (nj & 1) ? bb[2] : bb[0];
                    uint32_t b1 = (nj & 1) ? bb[3] : bb[1];
                    mma_f16(acc[mt][nj], af[mt], b0, b1);
                }
            }
        }
        if (i + 2 < NC) load_chunk(i + 2);
        else asm volatile("cp.async.commit_group;" ::: "memory");
    }

    if (SWI) {
        // drain pipeline, then reuse smem as output stage
        asm volatile("cp.async.wait_group 0;" ::: "memory");
        __syncthreads();
        __half* stage = (__half*)(smem + (dataA - smem_u32(smem)));
#pragma unroll
        for (int mt = 0; mt < 4; mt++) {
            int rr = warp_m + mt*16 + (lane >> 2);
#pragma unroll
            for (int nj = 0; nj < 4; nj++) {
                int hc = (warp_n >> 1) + nj*4 + (lane & 3);
                float a0 = acc[mt][nj][0], b0v = acc[mt][nj][1];
                float a1 = acc[mt][nj][2], b1v = acc[mt][nj][3];
                stage[rr * SWI_STRIDE + hc] =
                    __float2half_rn((a0 / (1.f + __expf(-a0))) * b0v);
                stage[(rr + 8) * SWI_STRIDE + hc] =
                    __float2half_rn((a1 / (1.f + __expf(-a1))) * b1v);
            }
        }
        __syncthreads();
        __half* G = (__half*)Cv;
        const int Nh = N >> 1;     // = FFN
        for (int t = tid; t < 128*8; t += 256) {
            int row = t >> 3, seg = t & 7;
            uint4 v = *(const uint4*)(stage + row * SWI_STRIDE + seg*8);
            *(uint4*)(G + (size_t)(bm + row) * Nh + (bn >> 1) + seg*8) = v;
        }
    } else {
#pragma unroll
        for (int mt = 0; mt < 4; mt++) {
            int row0g = bm + warp_m + mt*16 + (lane >> 2);
#pragma unroll
            for (int nj = 0; nj < 4; nj++) {
                int col = bn + warp_n + nj*8 + (lane & 3)*2;
                float* C = (float*)Cv;
                float b0 = 0.f, b1 = 0.f;
                if (bias) { b0 = bias[col]; b1 = bias[col+1]; }
                float* p0 = C + (size_t)row0g * N + col;
                float* p1 = C + (size_t)(row0g + 8) * N + col;
                float2 v0 = make_float2(acc[mt][nj][0] + b0, acc[mt][nj][1] + b1);
                float2 v1 = make_float2(acc[mt][nj][2] + b0, acc[mt][nj][3] + b1);
                if (resid) {
                    float2 r0 = *(const float2*)(resid + (size_t)row0g * N + col);
                    float2 r1 = *(const float2*)(resid + (size_t)(row0g + 8) * N + col);
                    v0.x += r0.x; v0.y += r0.y; v1.x += r1.x; v1.y += r1.y;
                }
                *(float2*)p0 = v0;
                *(float2*)p1 = v1;
            }
        }
    }
}

// ------------------------- RoPE (in-place on q,k of qkv) -------------------------
__global__ void rope_kernel(const int* __restrict__ positions, float* __restrict__ qkv) {
    int bs = blockIdx.x;
    int hh = blockIdx.y;
    int i  = threadIdx.x;
    float* base = qkv + (size_t)bs * QKV_DIM + hh * HD;
    float pos = (float)positions[bs];
    float freq = __expf(-(float)i * 0.14391565217f);
    float ang = pos * freq;
    float sn, cs;
    sincosf(ang, &sn, &cs);
    float x1 = base[i];
    float x2 = base[i + 64];
    base[i]      = x1 * cs - x2 * sn;
    base[i + 64] = x2 * cs + x1 * sn;
}

// ------------------------- flash attention (proven v1: 32 q-rows, 128 thr) ----
__global__ void __launch_bounds__(128) flash_attn_kernel(
    const float* __restrict__ qkv, __half* __restrict__ ah) {
    __shared__ __align__(16) float Qs[32][HD];
    __shared__ __align__(16) float KVs[32][HD];
    __shared__ float Ss[32][33];
    __shared__ float m_s[32], l_s[32], alpha_s[32];

    int qt = blockIdx.x;
    int h  = blockIdx.y;
    int b  = blockIdx.z;
    int kvh = h >> 4;
    int tid = threadIdx.x;
    int r  = tid >> 2;
    int qd = tid & 3;
    int q0 = qt * 32;

    for (int i = tid; i < 32*32; i += 128) {
        int row = i >> 5, c4 = i & 31;
        ((float4*)Qs[row])[c4] =
            *(const float4*)(qkv + (size_t)(b*SEQ + q0 + row) * QKV_DIM + h*HD + c4*4);
    }
    if (tid < 32) { m_s[tid] = -1e30f; l_s[tid] = 0.f; }
    float acc[32];
#pragma unroll
    for (int i = 0; i < 32; i++) acc[i] = 0.f;
    __syncthreads();

    const float scale = 0.08838834764831845f;

    for (int kt = 0; kt <= qt; kt++) {
        int k0 = kt * 32;
        for (int i = tid; i < 32*32; i += 128) {
            int row = i >> 5, c4 = i & 31;
            ((float4*)KVs[row])[c4] =
                *(const float4*)(qkv + (size_t)(b*SEQ + k0 + row) * QKV_DIM + K_OFF + kvh*HD + c4*4);
        }
        __syncthreads();

        int j0 = qd * 8;
        float sc[8];
#pragma unroll
        for (int jj = 0; jj < 8; jj++) sc[jj] = 0.f;
        const float4* q4 = (const float4*)Qs[r];
#pragma unroll 4
        for (int d4 = 0; d4 < 32; d4++) {
            float4 qv = q4[d4];
#pragma unroll
            for (int jj = 0; jj < 8; jj++) {
                float4 kv = ((const float4*)KVs[j0 + jj])[d4];
                sc[jj] += qv.x*kv.x + qv.y*kv.y + qv.z*kv.z + qv.w*kv.w;
            }
        }
#pragma unroll
        for (int jj = 0; jj < 8; jj++) {
            int kg = k0 + j0 + jj;
            Ss[r][j0 + jj] = (kg <= q0 + r) ? sc[jj] * scale : -1e30f;
        }
        __syncthreads();

        if (tid < 32) {
            float mx = m_s[tid];
            float tm = -1e30f;
#pragma unroll 8
            for (int j = 0; j < 32; j++) tm = fmaxf(tm, Ss[tid][j]);
            float mn = fmaxf(mx, tm);
            float al = __expf(mx - mn);
            float sum = 0.f;
#pragma unroll 8
            for (int j = 0; j < 32; j++) {
                float p = __expf(Ss[tid][j] - mn);
                Ss[tid][j] = p;
                sum += p;
            }
            m_s[tid] = mn;
            l_s[tid] = l_s[tid] * al + sum;
            alpha_s[tid] = al;
        }
        for (int i = tid; i < 32*32; i += 128) {
            int row = i >> 5, c4 = i & 31;
            ((float4*)KVs[row])[c4] =
                *(const float4*)(qkv + (size_t)(b*SEQ + k0 + row) * QKV_DIM + V_OFF + kvh*HD + c4*4);
        }
        __syncthreads();

        float al = alpha_s[r];
#pragma unroll
        for (int i = 0; i < 32; i++) acc[i] *= al;
#pragma unroll 4
        for (int j = 0; j < 32; j++) {
            float p = Ss[r][j];
            const float4* v4 = (const float4*)&KVs[j][qd*32];
#pragma unroll
            for (int i4 = 0; i4 < 8; i4++) {
                float4 vv = v4[i4];
                acc[i4*4+0] = fmaf(p, vv.x, acc[i4*4+0]);
                acc[i4*4+1] = fmaf(p, vv.y, acc[i4*4+1]);
                acc[i4*4+2] = fmaf(p, vv.z, acc[i4*4+2]);
                acc[i4*4+3] = fmaf(p, vv.w, acc[i4*4+3]);
            }
        }
        __syncthreads();
    }

    float invl = 1.f / l_s[r];
    uint2* o2 = (uint2*)(ah + (size_t)(b*SEQ + q0 + r) * HID + h*HD + qd*32);
#pragma unroll
    for (int i4 = 0; i4 < 8; i4++) {
        float4 o = make_float4(acc[i4*4+0]*invl, acc[i4*4+1]*invl,
                               acc[i4*4+2]*invl, acc[i4*4+3]*invl);
        o2[i4] = pack4h(o);
    }
}

// ------------------------- launch -------------------------
extern "C" void kernel_launch(void* const* d_in, const int* in_sizes, int n_in,
                              void* d_out, int out_size) {
    const int*   positions = (const int*)d_in[0];
    const float* hs        = (const float*)d_in[1];
    const float* ln1       = (const float*)d_in[2];
    const float* wqkv      = (const float*)d_in[3];
    const float* bqkv      = (const float*)d_in[4];
    const float* wo        = (const float*)d_in[5];
    const float* ln2       = (const float*)d_in[6];
    const float* w14       = (const float*)d_in[7];
    const float* w41       = (const float*)d_in[8];
    float* out = (float*)d_out;

    float *qkv, *attnout, *hidden;
    __half *wqkvh, *woh, *w14h, *w41h, *xh, *ah, *yh, *gh;
    cudaGetSymbolAddress((void**)&qkv,     g_qkv);
    cudaGetSymbolAddress((void**)&attnout, g_attnout);
    cudaGetSymbolAddress((void**)&hidden,  g_hidden);
    cudaGetSymbolAddress((void**)&wqkvh,   g_wqkvh);
    cudaGetSymbolAddress((void**)&woh,     g_woh);
    cudaGetSymbolAddress((void**)&w14h,    g_w14h);
    cudaGetSymbolAddress((void**)&w41h,    g_w41h);
    cudaGetSymbolAddress((void**)&xh,      g_xh);
    cudaGetSymbolAddress((void**)&ah,      g_ah);
    cudaGetSymbolAddress((void**)&yh,      g_yh);
    cudaGetSymbolAddress((void**)&gh,      g_gh);

    cudaFuncSetAttribute((const void*)&gemm_h<false>, cudaFuncAttributeMaxDynamicSharedMemorySize, GEMM_SMEM);
    cudaFuncSetAttribute((const void*)&gemm_h<true>,  cudaFuncAttributeMaxDynamicSharedMemorySize, GEMM_SMEM);

    // weight conversions (all plain fp16; w14 interleaved for SwiGLU fusion)
    {
        long long n4;
        n4 = (long long)QKV_DIM * HID / 4;
        round_f16_kernel<<<(unsigned)((n4+255)/256), 256>>>(wqkv, wqkvh, n4);
        n4 = (long long)HID * HID / 4;
        round_f16_kernel<<<(unsigned)((n4+255)/256), 256>>>(wo, woh, n4);
        n4 = (long long)(2*FFN) * HID / 4;
        round_f16_interleave_kernel<<<(unsigned)((n4+255)/256), 256>>>(w14, w14h, n4, HID/4);
        n4 = (long long)HID * FFN / 4;
        round_f16_kernel<<<(unsigned)((n4+255)/256), 256>>>(w41, w41h, n4);
    }

    // 1) xh = f16(rmsnorm(hs) * ln1)
    fused_norm_kernel<<<M_ROWS, 256>>>(nullptr, hs, ln1, nullptr, xh);

    // 2) qkv = x @ wqkv^T + bqkv
    gemm_h<false><<<16*36, 256, GEMM_SMEM>>>(xh, wqkvh, bqkv, nullptr, qkv, 36, HID, QKV_DIM);

    // 3) rope on q,k
    rope_kernel<<<dim3(M_ROWS, NH + NKV), 64>>>(positions, qkv);

    // 4) attention -> ah (fp16 ctx)
    flash_attn_kernel<<<dim3(SEQ/32, NH, BATCH), 128>>>(qkv, ah);

    // 5) attn_out = ctx @ wo^T
    gemm_h<false><<<16*32, 256, GEMM_SMEM>>>(ah, woh, nullptr, nullptr, attnout, 32, HID, HID);

    // 6) hidden = hs + attn_out ; yh = f16(rmsnorm(hidden) * ln2)
    fused_norm_kernel<<<M_ROWS, 256>>>(hs, attnout, ln2, hidden, yh);

    // 7) gh = f16(silu(a)*b) fused into FFN-up GEMM (interleaved w14, staged stores)
    gemm_h<true><<<16*214, 256, GEMM_SMEM>>>(yh, w14h, nullptr, nullptr, gh, 214, HID, 2*FFN);

    // 8) out = hidden + gated @ w41^T   (residual fused)
    gemm_h<false><<<16*32, 256, GEMM_SMEM>>>(gh, w41h, nullptr, hidden, out, 32, FFN, HID);
}

// round 15
// speedup vs baseline: 2.0279x; 1.0047x over previous
#include <cuda_runtime.h>
#include <cuda_fp16.h>
#include <math.h>
#include <stdint.h>

#define BATCH 2
#define SEQ 1024
#define HID 4096
#define NH 32
#define NKV 2
#define HD 128
#define FFN 13696
#define QKV_DIM ((NH + 2*NKV)*HD)   // 4608
#define M_ROWS (BATCH*SEQ)          // 2048
#define EPSV 1e-5f
#define V_OFF ((NH+NKV)*HD)         // 4352
#define K_OFF (NH*HD)               // 4096

// ------------------------- scratch (device globals) -------------------------
__device__ float g_qkv[(size_t)M_ROWS * QKV_DIM];
__device__ float g_attnout[(size_t)M_ROWS * HID];
__device__ float g_hidden[(size_t)M_ROWS * HID];
// fp16 weights (single plane). w14 rows PERMUTED: f -> 2f, FFN+f -> 2f+1.
__device__ __half g_wqkvh[(size_t)QKV_DIM * HID];
__device__ __half g_woh[(size_t)HID * HID];
__device__ __half g_w14h[(size_t)(2*FFN) * HID];
__device__ __half g_w41h[(size_t)HID * FFN];
// fp16 single activations
__device__ __half g_xh[(size_t)M_ROWS * HID];
__device__ __half g_ah[(size_t)M_ROWS * HID];
__device__ __half g_yh[(size_t)M_ROWS * HID];
__device__ __half g_gh[(size_t)M_ROWS * FFN];

// ------------------------- PTX helpers -------------------------
__device__ __forceinline__ uint32_t smem_u32(const void* p) {
    uint32_t a;
    asm("{ .reg .u64 t; cvta.to.shared.u64 t, %1; cvt.u32.u64 %0, t; }" : "=r"(a) : "l"(p));
    return a;
}
__device__ __forceinline__ void cp16(uint32_t s, const void* g) {
    asm volatile("cp.async.cg.shared.global [%0], [%1], 16;" :: "r"(s), "l"(g));
}
__device__ __forceinline__ void ldsm4(uint32_t* r, uint32_t addr) {
    asm volatile("ldmatrix.sync.aligned.m8n8.x4.shared.b16 {%0,%1,%2,%3}, [%4];"
                 : "=r"(r[0]), "=r"(r[1]), "=r"(r[2]), "=r"(r[3]) : "r"(addr));
}
__device__ __forceinline__ void mma_f16(float* c, const uint32_t* a, uint32_t b0, uint32_t b1) {
    asm volatile(
        "mma.sync.aligned.m16n8k16.row.col.f32.f16.f16.f32 "
        "{%0,%1,%2,%3}, {%4,%5,%6,%7}, {%8,%9}, {%0,%1,%2,%3};"
        : "+f"(c[0]), "+f"(c[1]), "+f"(c[2]), "+f"(c[3])
        : "r"(a[0]), "r"(a[1]), "r"(a[2]), "r"(a[3]), "r"(b0), "r"(b1));
}

// ------------------------- misc helpers -------------------------
__device__ __forceinline__ float warp_sum(float v) {
#pragma unroll
    for (int o = 16; o > 0; o >>= 1) v += __shfl_xor_sync(0xffffffffu, v, o);
    return v;
}
__device__ __forceinline__ uint2 pack4h(float4 v) {
    union { uint2 u; __half h[4]; } H;
    H.h[0] = __float2half_rn(v.x); H.h[1] = __float2half_rn(v.y);
    H.h[2] = __float2half_rn(v.z); H.h[3] = __float2half_rn(v.w);
    return H.u;
}

// ------------------------- weight conversion kernels -------------------------
__global__ void round_f16_kernel(const float* __restrict__ in,
                                 __half* __restrict__ out, long long n4) {
    long long i = (long long)blockIdx.x * blockDim.x + threadIdx.x;
    if (i >= n4) return;
    ((uint2*)out)[i] = pack4h(((const float4*)in)[i]);
}
// w14 conversion with SwiGLU row interleave: orig row f -> 2f, FFN+f -> 2f+1
__global__ void round_f16_interleave_kernel(const float* __restrict__ in,
                                            __half* __restrict__ out,
                                            long long n4, int kq) {
    long long i = (long long)blockIdx.x * blockDim.x + threadIdx.x;
    if (i >= n4) return;
    long long n = i / kq;
    long long k4 = i - n * kq;
    long long nn = (n < FFN) ? 2*n : 2*(n - FFN) + 1;
    ((uint2*)out)[nn * kq + k4] = pack4h(((const float4*)in)[i]);
}

// ------------------------- fused (add+)rmsnorm -> fp16 single -------------------------
__global__ void __launch_bounds__(256) fused_norm_kernel(
    const float* __restrict__ res, const float* __restrict__ x,
    const float* __restrict__ w, float* __restrict__ hid_out,
    __half* __restrict__ yh) {
    __shared__ __align__(16) float buf[HID];
    __shared__ float red[8];
    int row = blockIdx.x;
    size_t base = (size_t)row * HID;
    const float4* x4 = (const float4*)(x + base);
    const float4* r4 = res ? (const float4*)(res + base) : nullptr;
    float4* b4 = (float4*)buf;

    float ss = 0.f;
    for (int i = threadIdx.x; i < HID/4; i += 256) {
        float4 v = x4[i];
        if (r4) { float4 rr = r4[i]; v.x += rr.x; v.y += rr.y; v.z += rr.z; v.w += rr.w; }
        b4[i] = v;
        ss += v.x*v.x + v.y*v.y + v.z*v.z + v.w*v.w;
    }
    ss = warp_sum(ss);
    if ((threadIdx.x & 31) == 0) red[threadIdx.x >> 5] = ss;
    __syncthreads();
    float tot = 0.f;
#pragma unroll
    for (int i = 0; i < 8; i++) tot += red[i];
    float inv = rsqrtf(tot / (float)HID + EPSV);

    float4* h4 = hid_out ? (float4*)(hid_out + base) : nullptr;
    const float4* w4 = (const float4*)w;
    uint2* y2 = (uint2*)(yh + base);
    for (int i = threadIdx.x; i < HID/4; i += 256) {
        float4 v = b4[i];
        if (h4) h4[i] = v;
        float4 ww = w4[i];
        float4 o;
        o.x = v.x * inv * ww.x; o.y = v.y * inv * ww.y;
        o.z = v.z * inv * ww.z; o.w = v.w * inv * ww.w;
        y2[i] = pack4h(o);
    }
}

// ------------------------- fp16 1-phase HMMA GEMM -------------------------
#define NSTAGE 3
#define STAGE_BYTES 32768
#define GEMM_SMEM (NSTAGE * STAGE_BYTES + 1024)
#define SWI_STRIDE 72

template<bool SWI>
__global__ void __launch_bounds__(256, 2) gemm_h(
    const __half* __restrict__ Av, const __half* __restrict__ Bv,
    const float* __restrict__ bias, const float* __restrict__ resid,
    void* __restrict__ Cv, int NT, int Kel, int N) {
    extern __shared__ char smem[];
    uint32_t dataA = (smem_u32(smem) + 1023) & ~1023u;
    int tid = threadIdx.x;
    int wid = tid >> 5, lane = tid & 31;

    int g = blockIdx.x / (16*18);
    int r = blockIdx.x % (16*18);
    int gn = NT - g*18; if (gn > 18) gn = 18;
    int bn = (g*18 + r % gn) * 128;
    int bm = (r / gn) * 128;

    const size_t rowb = (size_t)Kel * 2;
    const char* Abase = (const char*)Av + (size_t)bm * rowb;
    const char* Bbase = (const char*)Bv + (size_t)bn * rowb;
    const int NC = Kel >> 6;
    const int c16 = (tid & 7) * 16;
    const int row0 = tid >> 3;

    auto load_chunk = [&](int j) {
        size_t off = (size_t)j * 128 + c16;
        int s = j % NSTAGE;
        uint32_t sA = dataA + s*STAGE_BYTES;
        uint32_t sB = sA + 16384;
#pragma unroll
        for (int p = 0; p < 4; p++) {
            int row = row0 + p*32;
            uint32_t sw = row*128 + (c16 ^ ((row & 7) << 4));
            cp16(sA + sw, Abase + (size_t)row * rowb + off);
            cp16(sB + sw, Bbase + (size_t)row * rowb + off);
        }
        asm volatile("cp.async.commit_group;" ::: "memory");
    };

    float acc[4][4][4];
#pragma unroll
    for (int a = 0; a < 4; a++)
#pragma unroll
        for (int b = 0; b < 4; b++)
#pragma unroll
            for (int c = 0; c < 4; c++) acc[a][b][c] = 0.f;

    const int warp_m = (wid & 1) * 64;
    const int warp_n = (wid >> 1) * 32;

    load_chunk(0);
    load_chunk(1);

    for (int i = 0; i < NC; i++) {
        asm volatile("cp.async.wait_group 1;" ::: "memory");
        __syncthreads();

        uint32_t sA = dataA + (i % NSTAGE)*STAGE_BYTES;
        uint32_t sB = sA + 16384;
#pragma unroll
        for (int ks = 0; ks < 4; ks++) {
            int kb = ks * 32;
            uint32_t af[4][4];
#pragma unroll
            for (int mt = 0; mt < 4; mt++) {
                int rw = warp_m + mt*16 + (lane & 15);
                int cb = kb + ((lane >> 4) << 4);
                ldsm4(af[mt], sA + rw*128 + (cb ^ ((rw & 7) << 4)));
            }
            uint32_t bf[2][4];
#pragma unroll
            for (int nt = 0; nt < 2; nt++) {
                int nr = warp_n + nt*16 + ((lane >> 4) << 3) + (lane & 7);
                int cb = kb + (((lane >> 3) & 1) << 4);
                ldsm4(bf[nt], sB + nr*128 + (cb ^ ((nr & 7) << 4)));
            }
#pragma unroll
            for (int mt = 0; mt < 4; mt++) {
#pragma unroll
                for (int nj = 0; nj < 4; nj++) {
                    const uint32_t* bb = bf[nj >> 1];
                    uint32_t b0 = (nj & 1) ? bb[2] : bb[0];
                    uint32_t b1 = (nj & 1) ? bb[3] : bb[1];
                    mma_f16(acc[mt][nj], af[mt], b0, b1);
                }
            }
        }
        if (i + 2 < NC) load_chunk(i + 2);
        else asm volatile("cp.async.commit_group;" ::: "memory");
    }

    if (SWI) {
        asm volatile("cp.async.wait_group 0;" ::: "memory");
        __syncthreads();
        __half* stage = (__half*)(smem + (dataA - smem_u32(smem)));
#pragma unroll
        for (int mt = 0; mt < 4; mt++) {
            int rr = warp_m + mt*16 + (lane >> 2);
#pragma unroll
            for (int nj = 0; nj < 4; nj++) {
                int hc = (warp_n >> 1) + nj*4 + (lane & 3);
                float a0 = acc[mt][nj][0], b0v = acc[mt][nj][1];
                float a1 = acc[mt][nj][2], b1v = acc[mt][nj][3];
                stage[rr * SWI_STRIDE + hc] =
                    __float2half_rn((a0 / (1.f + __expf(-a0))) * b0v);
                stage[(rr + 8) * SWI_STRIDE + hc] =
                    __float2half_rn((a1 / (1.f + __expf(-a1))) * b1v);
            }
        }
        __syncthreads();
        __half* G = (__half*)Cv;
        const int Nh = N >> 1;
        for (int t = tid; t < 128*8; t += 256) {
            int row = t >> 3, seg = t & 7;
            uint4 v = *(const uint4*)(stage + row * SWI_STRIDE + seg*8);
            *(uint4*)(G + (size_t)(bm + row) * Nh + (bn >> 1) + seg*8) = v;
        }
    } else {
#pragma unroll
        for (int mt = 0; mt < 4; mt++) {
            int row0g = bm + warp_m + mt*16 + (lane >> 2);
#pragma unroll
            for (int nj = 0; nj < 4; nj++) {
                int col = bn + warp_n + nj*8 + (lane & 3)*2;
                float* C = (float*)Cv;
                float b0 = 0.f, b1 = 0.f;
                if (bias) { b0 = bias[col]; b1 = bias[col+1]; }
                float* p0 = C + (size_t)row0g * N + col;
                float* p1 = C + (size_t)(row0g + 8) * N + col;
                float2 v0 = make_float2(acc[mt][nj][0] + b0, acc[mt][nj][1] + b1);
                float2 v1 = make_float2(acc[mt][nj][2] + b0, acc[mt][nj][3] + b1);
                if (resid) {
                    float2 r0 = *(const float2*)(resid + (size_t)row0g * N + col);
                    float2 r1 = *(const float2*)(resid + (size_t)(row0g + 8) * N + col);
                    v0.x += r0.x; v0.y += r0.y; v1.x += r1.x; v1.y += r1.y;
                }
                *(float2*)p0 = v0;
                *(float2*)p1 = v1;
            }
        }
    }
}

// ------------------------- RoPE (in-place on q,k of qkv) -------------------------
__global__ void rope_kernel(const int* __restrict__ positions, float* __restrict__ qkv) {
    int bs = blockIdx.x;
    int hh = blockIdx.y;
    int i  = threadIdx.x;
    float* base = qkv + (size_t)bs * QKV_DIM + hh * HD;
    float pos = (float)positions[bs];
    float freq = __expf(-(float)i * 0.14391565217f);
    float ang = pos * freq;
    float sn, cs;
    sincosf(ang, &sn, &cs);
    float x1 = base[i];
    float x2 = base[i + 64];
    base[i]      = x1 * cs - x2 * sn;
    base[i + 64] = x2 * cs + x1 * sn;
}

// ------------------------- flash attention v1 + register softmax ----------------
// 32 q-rows, 128 threads. Softmax in registers (shfl over the 4 lanes of a row);
// m/l/alpha per-thread (replicated x4). V-load issued before softmax math.
__global__ void __launch_bounds__(128) flash_attn_kernel(
    const float* __restrict__ qkv, __half* __restrict__ ah) {
    __shared__ __align__(16) float Qs[32][HD];
    __shared__ __align__(16) float KVs[32][HD];
    __shared__ float Ss[32][33];

    int qt = blockIdx.x;
    int h  = blockIdx.y;
    int b  = blockIdx.z;
    int kvh = h >> 4;
    int tid = threadIdx.x;
    int r  = tid >> 2;
    int qd = tid & 3;
    int q0 = qt * 32;

    for (int i = tid; i < 32*32; i += 128) {
        int row = i >> 5, c4 = i & 31;
        ((float4*)Qs[row])[c4] =
            *(const float4*)(qkv + (size_t)(b*SEQ + q0 + row) * QKV_DIM + h*HD + c4*4);
    }
    float m_reg = -1e30f, l_reg = 0.f;
    float acc[32];
#pragma unroll
    for (int i = 0; i < 32; i++) acc[i] = 0.f;
    __syncthreads();

    const float scale = 0.08838834764831845f;

    for (int kt = 0; kt <= qt; kt++) {
        int k0 = kt * 32;
        // load K tile
        for (int i = tid; i < 32*32; i += 128) {
            int row = i >> 5, c4 = i & 31;
            ((float4*)KVs[row])[c4] =
                *(const float4*)(qkv + (size_t)(b*SEQ + k0 + row) * QKV_DIM + K_OFF + kvh*HD + c4*4);
        }
        __syncthreads();

        // scores for keys j0..j0+7 of row r
        int j0 = qd * 8;
        float sc[8];
#pragma unroll
        for (int jj = 0; jj < 8; jj++) sc[jj] = 0.f;
        const float4* q4 = (const float4*)Qs[r];
#pragma unroll 4
        for (int d4 = 0; d4 < 32; d4++) {
            float4 qv = q4[d4];
#pragma unroll
            for (int jj = 0; jj < 8; jj++) {
                float4 kv = ((const float4*)KVs[j0 + jj])[d4];
                sc[jj] += qv.x*kv.x + qv.y*kv.y + qv.z*kv.z + qv.w*kv.w;
            }
        }
#pragma unroll
        for (int jj = 0; jj < 8; jj++) {
            int kg = k0 + j0 + jj;
            sc[jj] = (kg <= q0 + r) ? sc[jj] * scale : -1e30f;
        }
        __syncthreads();    // all threads done reading K from KVs

        // issue V load immediately (overlaps with softmax math below)
        for (int i = tid; i < 32*32; i += 128) {
            int row = i >> 5, c4 = i & 31;
            ((float4*)KVs[row])[c4] =
                *(const float4*)(qkv + (size_t)(b*SEQ + k0 + row) * QKV_DIM + V_OFF + kvh*HD + c4*4);
        }

        // register softmax: reduce across the row's 4 lanes via shfl
        float tmax = sc[0];
#pragma unroll
        for (int jj = 1; jj < 8; jj++) tmax = fmaxf(tmax, sc[jj]);
        tmax = fmaxf(tmax, __shfl_xor_sync(0xffffffffu, tmax, 1));
        tmax = fmaxf(tmax, __shfl_xor_sync(0xffffffffu, tmax, 2));
        float mn = fmaxf(m_reg, tmax);
        float al = __expf(m_reg - mn);
        float sum = 0.f;
#pragma unroll
        for (int jj = 0; jj < 8; jj++) {
            float p = __expf(sc[jj] - mn);
            Ss[r][j0 + jj] = p;
            sum += p;
        }
        sum += __shfl_xor_sync(0xffffffffu, sum, 1);
        sum += __shfl_xor_sync(0xffffffffu, sum, 2);
        m_reg = mn;
        l_reg = l_reg * al + sum;

        __syncthreads();    // V tile + Ss visible

        // rescale + P@V
#pragma unroll
        for (int i = 0; i < 32; i++) acc[i] *= al;
        const float* prow = Ss[r];
#pragma unroll 4
        for (int j = 0; j < 32; j++) {
            float p = prow[j];
            const float4* v4 = (const float4*)&KVs[j][qd*32];
#pragma unroll
            for (int i4 = 0; i4 < 8; i4++) {
                float4 vv = v4[i4];
                acc[i4*4+0] = fmaf(p, vv.x, acc[i4*4+0]);
                acc[i4*4+1] = fmaf(p, vv.y, acc[i4*4+1]);
                acc[i4*4+2] = fmaf(p, vv.z, acc[i4*4+2]);
                acc[i4*4+3] = fmaf(p, vv.w, acc[i4*4+3]);
            }
        }
        __syncthreads();    // PV readers done before next K load
    }

    float invl = 1.f / l_reg;
    uint2* o2 = (uint2*)(ah + (size_t)(b*SEQ + q0 + r) * HID + h*HD + qd*32);
#pragma unroll
    for (int i4 = 0; i4 < 8; i4++) {
        float4 o = make_float4(acc[i4*4+0]*invl, acc[i4*4+1]*invl,
                               acc[i4*4+2]*invl, acc[i4*4+3]*invl);
        o2[i4] = pack4h(o);
    }
}

// ------------------------- launch -------------------------
extern "C" void kernel_launch(void* const* d_in, const int* in_sizes, int n_in,
                              void* d_out, int out_size) {
    const int*   positions = (const int*)d_in[0];
    const float* hs        = (const float*)d_in[1];
    const float* ln1       = (const float*)d_in[2];
    const float* wqkv      = (const float*)d_in[3];
    const float* bqkv      = (const float*)d_in[4];
    const float* wo        = (const float*)d_in[5];
    const float* ln2       = (const float*)d_in[6];
    const float* w14       = (const float*)d_in[7];
    const float* w41       = (const float*)d_in[8];
    float* out = (float*)d_out;

    float *qkv, *attnout, *hidden;
    __half *wqkvh, *woh, *w14h, *w41h, *xh, *ah, *yh, *gh;
    cudaGetSymbolAddress((void**)&qkv,     g_qkv);
    cudaGetSymbolAddress((void**)&attnout, g_attnout);
    cudaGetSymbolAddress((void**)&hidden,  g_hidden);
    cudaGetSymbolAddress((void**)&wqkvh,   g_wqkvh);
    cudaGetSymbolAddress((void**)&woh,     g_woh);
    cudaGetSymbolAddress((void**)&w14h,    g_w14h);
    cudaGetSymbolAddress((void**)&w41h,    g_w41h);
    cudaGetSymbolAddress((void**)&xh,      g_xh);
    cudaGetSymbolAddress((void**)&ah,      g_ah);
    cudaGetSymbolAddress((void**)&yh,      g_yh);
    cudaGetSymbolAddress((void**)&gh,      g_gh);

    cudaFuncSetAttribute((const void*)&gemm_h<false>, cudaFuncAttributeMaxDynamicSharedMemorySize, GEMM_SMEM);
    cudaFuncSetAttribute((const void*)&gemm_h<true>,  cudaFuncAttributeMaxDynamicSharedMemorySize, GEMM_SMEM);

    // weight conversions (all plain fp16; w14 interleaved for SwiGLU fusion)
    {
        long long n4;
        n4 = (long long)QKV_DIM * HID / 4;
        round_f16_kernel<<<(unsigned)((n4+255)/256), 256>>>(wqkv, wqkvh, n4);
        n4 = (long long)HID * HID / 4;
        round_f16_kernel<<<(unsigned)((n4+255)/256), 256>>>(wo, woh, n4);
        n4 = (long long)(2*FFN) * HID / 4;
        round_f16_interleave_kernel<<<(unsigned)((n4+255)/256), 256>>>(w14, w14h, n4, HID/4);
        n4 = (long long)HID * FFN / 4;
        round_f16_kernel<<<(unsigned)((n4+255)/256), 256>>>(w41, w41h, n4);
    }

    // 1) xh = f16(rmsnorm(hs) * ln1)
    fused_norm_kernel<<<M_ROWS, 256>>>(nullptr, hs, ln1, nullptr, xh);

    // 2) qkv = x @ wqkv^T + bqkv
    gemm_h<false><<<16*36, 256, GEMM_SMEM>>>(xh, wqkvh, bqkv, nullptr, qkv, 36, HID, QKV_DIM);

    // 3) rope on q,k
    rope_kernel<<<dim3(M_ROWS, NH + NKV), 64>>>(positions, qkv);

    // 4) attention -> ah (fp16 ctx)
    flash_attn_kernel<<<dim3(SEQ/32, NH, BATCH), 128>>>(qkv, ah);

    // 5) attn_out = ctx @ wo^T
    gemm_h<false><<<16*32, 256, GEMM_SMEM>>>(ah, woh, nullptr, nullptr, attnout, 32, HID, HID);

    // 6) hidden = hs + attn_out ; yh = f16(rmsnorm(hidden) * ln2)
    fused_norm_kernel<<<M_ROWS, 256>>>(hs, attnout, ln2, hidden, yh);

    // 7) gh = f16(silu(a)*b) fused into FFN-up GEMM (interleaved w14, staged stores)
    gemm_h<true><<<16*214, 256, GEMM_SMEM>>>(yh, w14h, nullptr, nullptr, gh, 214, HID, 2*FFN);

    // 8) out = hidden + gated @ w41^T   (residual fused)
    gemm_h<false><<<16*32, 256, GEMM_SMEM>>>(gh, w41h, nullptr, hidden, out, 32, FFN, HID);
}

// round 16
// speedup vs baseline: 2.1291x; 1.0499x over previous
#include <cuda_runtime.h>
#include <cuda_fp16.h>
#include <math.h>
#include <stdint.h>

#define BATCH 2
#define SEQ 1024
#define HID 4096
#define NH 32
#define NKV 2
#define HD 128
#define FFN 13696
#define QKV_DIM ((NH + 2*NKV)*HD)   // 4608
#define M_ROWS (BATCH*SEQ)          // 2048
#define EPSV 1e-5f
#define V_OFF ((NH+NKV)*HD)         // 4352
#define K_OFF (NH*HD)               // 4096

// ------------------------- scratch (device globals) -------------------------
__device__ float g_qkv[(size_t)M_ROWS * QKV_DIM];
__device__ float g_attnout[(size_t)M_ROWS * HID];
__device__ float g_hidden[(size_t)M_ROWS * HID];
// fp16 weights (single plane). w14 rows PERMUTED: f -> 2f, FFN+f -> 2f+1.
__device__ __half g_wqkvh[(size_t)QKV_DIM * HID];
__device__ __half g_woh[(size_t)HID * HID];
__device__ __half g_w14h[(size_t)(2*FFN) * HID];
__device__ __half g_w41h[(size_t)HID * FFN];
// fp16 single activations
__device__ __half g_xh[(size_t)M_ROWS * HID];
__device__ __half g_ah[(size_t)M_ROWS * HID];
__device__ __half g_yh[(size_t)M_ROWS * HID];
__device__ __half g_gh[(size_t)M_ROWS * FFN];

// ------------------------- PTX helpers -------------------------
__device__ __forceinline__ uint32_t smem_u32(const void* p) {
    uint32_t a;
    asm("{ .reg .u64 t; cvta.to.shared.u64 t, %1; cvt.u32.u64 %0, t; }" : "=r"(a) : "l"(p));
    return a;
}
__device__ __forceinline__ void cp16(uint32_t s, const void* g) {
    asm volatile("cp.async.cg.shared.global [%0], [%1], 16;" :: "r"(s), "l"(g));
}
__device__ __forceinline__ void ldsm4(uint32_t* r, uint32_t addr) {
    asm volatile("ldmatrix.sync.aligned.m8n8.x4.shared.b16 {%0,%1,%2,%3}, [%4];"
                 : "=r"(r[0]), "=r"(r[1]), "=r"(r[2]), "=r"(r[3]) : "r"(addr));
}
__device__ __forceinline__ void mma_f16(float* c, const uint32_t* a, uint32_t b0, uint32_t b1) {
    asm volatile(
        "mma.sync.aligned.m16n8k16.row.col.f32.f16.f16.f32 "
        "{%0,%1,%2,%3}, {%4,%5,%6,%7}, {%8,%9}, {%0,%1,%2,%3};"
        : "+f"(c[0]), "+f"(c[1]), "+f"(c[2]), "+f"(c[3])
        : "r"(a[0]), "r"(a[1]), "r"(a[2]), "r"(a[3]), "r"(b0), "r"(b1));
}

// ------------------------- misc helpers -------------------------
__device__ __forceinline__ float warp_sum(float v) {
#pragma unroll
    for (int o = 16; o > 0; o >>= 1) v += __shfl_xor_sync(0xffffffffu, v, o);
    return v;
}
__device__ __forceinline__ uint2 pack4h(float4 v) {
    union { uint2 u; __half h[4]; } H;
    H.h[0] = __float2half_rn(v.x); H.h[1] = __float2half_rn(v.y);
    H.h[2] = __float2half_rn(v.z); H.h[3] = __float2half_rn(v.w);
    return H.u;
}

// ------------------------- weight conversion kernels -------------------------
__global__ void round_f16_kernel(const float* __restrict__ in,
                                 __half* __restrict__ out, long long n4) {
    long long i = (long long)blockIdx.x * blockDim.x + threadIdx.x;
    if (i >= n4) return;
    ((uint2*)out)[i] = pack4h(((const float4*)in)[i]);
}
// w14 conversion with SwiGLU row interleave: orig row f -> 2f, FFN+f -> 2f+1
__global__ void round_f16_interleave_kernel(const float* __restrict__ in,
                                            __half* __restrict__ out,
                                            long long n4, int kq) {
    long long i = (long long)blockIdx.x * blockDim.x + threadIdx.x;
    if (i >= n4) return;
    long long n = i / kq;
    long long k4 = i - n * kq;
    long long nn = (n < FFN) ? 2*n : 2*(n - FFN) + 1;
    ((uint2*)out)[nn * kq + k4] = pack4h(((const float4*)in)[i]);
}

// ------------------------- fused (add+)rmsnorm -> fp16 single -------------------------
__global__ void __launch_bounds__(256) fused_norm_kernel(
    const float* __restrict__ res, const float* __restrict__ x,
    const float* __restrict__ w, float* __restrict__ hid_out,
    __half* __restrict__ yh) {
    __shared__ __align__(16) float buf[HID];
    __shared__ float red[8];
    int row = blockIdx.x;
    size_t base = (size_t)row * HID;
    const float4* x4 = (const float4*)(x + base);
    const float4* r4 = res ? (const float4*)(res + base) : nullptr;
    float4* b4 = (float4*)buf;

    float ss = 0.f;
    for (int i = threadIdx.x; i < HID/4; i += 256) {
        float4 v = x4[i];
        if (r4) { float4 rr = r4[i]; v.x += rr.x; v.y += rr.y; v.z += rr.z; v.w += rr.w; }
        b4[i] = v;
        ss += v.x*v.x + v.y*v.y + v.z*v.z + v.w*v.w;
    }
    ss = warp_sum(ss);
    if ((threadIdx.x & 31) == 0) red[threadIdx.x >> 5] = ss;
    __syncthreads();
    float tot = 0.f;
#pragma unroll
    for (int i = 0; i < 8; i++) tot += red[i];
    float inv = rsqrtf(tot / (float)HID + EPSV);

    float4* h4 = hid_out ? (float4*)(hid_out + base) : nullptr;
    const float4* w4 = (const float4*)w;
    uint2* y2 = (uint2*)(yh + base);
    for (int i = threadIdx.x; i < HID/4; i += 256) {
        float4 v = b4[i];
        if (h4) h4[i] = v;
        float4 ww = w4[i];
        float4 o;
        o.x = v.x * inv * ww.x; o.y = v.y * inv * ww.y;
        o.z = v.z * inv * ww.z; o.w = v.w * inv * ww.w;
        y2[i] = pack4h(o);
    }
}

// ------------------------- fp16 1-phase HMMA GEMM -------------------------
#define NSTAGE 3
#define STAGE_BYTES 32768
#define GEMM_SMEM (NSTAGE * STAGE_BYTES + 1024)
#define SWI_STRIDE 72

template<bool SWI>
__global__ void __launch_bounds__(256, 2) gemm_h(
    const __half* __restrict__ Av, const __half* __restrict__ Bv,
    const float* __restrict__ bias, const float* __restrict__ resid,
    void* __restrict__ Cv, int NT, int Kel, int N) {
    extern __shared__ char smem[];
    uint32_t dataA = (smem_u32(smem) + 1023) & ~1023u;
    int tid = threadIdx.x;
    int wid = tid >> 5, lane = tid & 31;

    int g = blockIdx.x / (16*18);
    int r = blockIdx.x % (16*18);
    int gn = NT - g*18; if (gn > 18) gn = 18;
    int bn = (g*18 + r % gn) * 128;
    int bm = (r / gn) * 128;

    const size_t rowb = (size_t)Kel * 2;
    const char* Abase = (const char*)Av + (size_t)bm * rowb;
    const char* Bbase = (const char*)Bv + (size_t)bn * rowb;
    const int NC = Kel >> 6;
    const int c16 = (tid & 7) * 16;
    const int row0 = tid >> 3;

    auto load_chunk = [&](int j) {
        size_t off = (size_t)j * 128 + c16;
        int s = j % NSTAGE;
        uint32_t sA = dataA + s*STAGE_BYTES;
        uint32_t sB = sA + 16384;
#pragma unroll
        for (int p = 0; p < 4; p++) {
            int row = row0 + p*32;
            uint32_t sw = row*128 + (c16 ^ ((row & 7) << 4));
            cp16(sA + sw, Abase + (size_t)row * rowb + off);
            cp16(sB + sw, Bbase + (size_t)row * rowb + off);
        }
        asm volatile("cp.async.commit_group;" ::: "memory");
    };

    float acc[4][4][4];
#pragma unroll
    for (int a = 0; a < 4; a++)
#pragma unroll
        for (int b = 0; b < 4; b++)
#pragma unroll
            for (int c = 0; c < 4; c++) acc[a][b][c] = 0.f;

    const int warp_m = (wid & 1) * 64;
    const int warp_n = (wid >> 1) * 32;

    load_chunk(0);
    load_chunk(1);

    for (int i = 0; i < NC; i++) {
        asm volatile("cp.async.wait_group 1;" ::: "memory");
        __syncthreads();

        uint32_t sA = dataA + (i % NSTAGE)*STAGE_BYTES;
        uint32_t sB = sA + 16384;
#pragma unroll
        for (int ks = 0; ks < 4; ks++) {
            int kb = ks * 32;
            uint32_t af[4][4];
#pragma unroll
            for (int mt = 0; mt < 4; mt++) {
                int rw = warp_m + mt*16 + (lane & 15);
                int cb = kb + ((lane >> 4) << 4);
                ldsm4(af[mt], sA + rw*128 + (cb ^ ((rw & 7) << 4)));
            }
            uint32_t bf[2][4];
#pragma unroll
            for (int nt = 0; nt < 2; nt++) {
                int nr = warp_n + nt*16 + ((lane >> 4) << 3) + (lane & 7);
                int cb = kb + (((lane >> 3) & 1) << 4);
                ldsm4(bf[nt], sB + nr*128 + (cb ^ ((nr & 7) << 4)));
            }
#pragma unroll
            for (int mt = 0; mt < 4; mt++) {
#pragma unroll
                for (int nj = 0; nj < 4; nj++) {
                    const uint32_t* bb = bf[nj >> 1];
                    uint32_t b0 = (nj & 1) ? bb[2] : bb[0];
                    uint32_t b1 = (nj & 1) ? bb[3] : bb[1];
                    mma_f16(acc[mt][nj], af[mt], b0, b1);
                }
            }
        }
        if (i + 2 < NC) load_chunk(i + 2);
        else asm volatile("cp.async.commit_group;" ::: "memory");
    }

    if (SWI) {
        asm volatile("cp.async.wait_group 0;" ::: "memory");
        __syncthreads();
        __half* stage = (__half*)(smem + (dataA - smem_u32(smem)));
#pragma unroll
        for (int mt = 0; mt < 4; mt++) {
            int rr = warp_m + mt*16 + (lane >> 2);
#pragma unroll
            for (int nj = 0; nj < 4; nj++) {
                int hc = (warp_n >> 1) + nj*4 + (lane & 3);
                float a0 = acc[mt][nj][0], b0v = acc[mt][nj][1];
                float a1 = acc[mt][nj][2], b1v = acc[mt][nj][3];
                stage[rr * SWI_STRIDE + hc] =
                    __float2half_rn((a0 / (1.f + __expf(-a0))) * b0v);
                stage[(rr + 8) * SWI_STRIDE + hc] =
                    __float2half_rn((a1 / (1.f + __expf(-a1))) * b1v);
            }
        }
        __syncthreads();
        __half* G = (__half*)Cv;
        const int Nh = N >> 1;
        for (int t = tid; t < 128*8; t += 256) {
            int row = t >> 3, seg = t & 7;
            uint4 v = *(const uint4*)(stage + row * SWI_STRIDE + seg*8);
            *(uint4*)(G + (size_t)(bm + row) * Nh + (bn >> 1) + seg*8) = v;
        }
    } else {
#pragma unroll
        for (int mt = 0; mt < 4; mt++) {
            int row0g = bm + warp_m + mt*16 + (lane >> 2);
#pragma unroll
            for (int nj = 0; nj < 4; nj++) {
                int col = bn + warp_n + nj*8 + (lane & 3)*2;
                float* C = (float*)Cv;
                float b0 = 0.f, b1 = 0.f;
                if (bias) { b0 = bias[col]; b1 = bias[col+1]; }
                float* p0 = C + (size_t)row0g * N + col;
                float* p1 = C + (size_t)(row0g + 8) * N + col;
                float2 v0 = make_float2(acc[mt][nj][0] + b0, acc[mt][nj][1] + b1);
                float2 v1 = make_float2(acc[mt][nj][2] + b0, acc[mt][nj][3] + b1);
                if (resid) {
                    float2 r0 = *(const float2*)(resid + (size_t)row0g * N + col);
                    float2 r1 = *(const float2*)(resid + (size_t)(row0g + 8) * N + col);
                    v0.x += r0.x; v0.y += r0.y; v1.x += r1.x; v1.y += r1.y;
                }
                *(float2*)p0 = v0;
                *(float2*)p1 = v1;
            }
        }
    }
}

// ------------------------- RoPE (in-place on q,k of qkv) -------------------------
__global__ void rope_kernel(const int* __restrict__ positions, float* __restrict__ qkv) {
    int bs = blockIdx.x;
    int hh = blockIdx.y;
    int i  = threadIdx.x;
    float* base = qkv + (size_t)bs * QKV_DIM + hh * HD;
    float pos = (float)positions[bs];
    float freq = __expf(-(float)i * 0.14391565217f);
    float ang = pos * freq;
    float sn, cs;
    sincosf(ang, &sn, &cs);
    float x1 = base[i];
    float x2 = base[i + 64];
    base[i]      = x1 * cs - x2 * sn;
    base[i + 64] = x2 * cs + x1 * sn;
}

// ------------------------- flash attention: cp.async double-buffered K+V ---------
// 32 q-rows, 128 threads, register softmax (R15 arithmetic, identical results).
// KV tiles prefetched one tile ahead via cp.async; 3 barriers/tile.
// smem: Q[32*128] | stage0{K,V} | stage1{K,V} | Ss[32*33]  = ~84KB dynamic.
#define ATT_SMEM ((4096 + 2*8192 + 32*33) * 4)

__global__ void __launch_bounds__(128) flash_attn_kernel(
    const float* __restrict__ qkv, __half* __restrict__ ah) {
    extern __shared__ float sm[];
    float* Qs  = sm;                    // [32][128]
    float* KV0 = sm + 4096;             // stage s: K at +s*8192, V at +s*8192+4096
    float* Ss  = sm + 4096 + 16384;     // [32][33]

    int qt = blockIdx.x;
    int h  = blockIdx.y;
    int b  = blockIdx.z;
    int kvh = h >> 4;
    int tid = threadIdx.x;
    int r  = tid >> 2;
    int qd = tid & 3;
    int q0 = qt * 32;

    auto load_kv = [&](int kt, int s) {
        uint32_t base = smem_u32(KV0 + s * 8192);
        for (int i = tid; i < 32*32; i += 128) {
            int row = i >> 5, c4 = i & 31;
            const float* g = qkv + (size_t)(b*SEQ + kt*32 + row) * QKV_DIM + kvh*HD + c4*4;
            cp16(base + (row*HD + c4*4)*4, g + K_OFF);
            cp16(base + (4096 + row*HD + c4*4)*4, g + V_OFF);
        }
        asm volatile("cp.async.commit_group;" ::: "memory");
    };

    // prefetch tile 0, load Q with plain stores
    load_kv(0, 0);
    for (int i = tid; i < 32*32; i += 128) {
        int row = i >> 5, c4 = i & 31;
        ((float4*)(Qs + row*HD))[c4] =
            *(const float4*)(qkv + (size_t)(b*SEQ + q0 + row) * QKV_DIM + h*HD + c4*4);
    }

    float m_reg = -1e30f, l_reg = 0.f;
    float acc[32];
#pragma unroll
    for (int i = 0; i < 32; i++) acc[i] = 0.f;

    const float scale = 0.08838834764831845f;

    for (int kt = 0; kt <= qt; kt++) {
        int cur = kt & 1;
        int k0 = kt * 32;
        // issue next tile into the opposite stage (safe: last-iter trailing
        // barrier guaranteed all threads finished reading it)
        if (kt < qt) {
            load_kv(kt + 1, cur ^ 1);
            asm volatile("cp.async.wait_group 1;" ::: "memory");
        } else {
            asm volatile("cp.async.wait_group 0;" ::: "memory");
        }
        __syncthreads();   // current stage (and Q on first iter) visible to all

        const float* Ks = KV0 + cur * 8192;
        const float* Vs = Ks + 4096;

        // scores for keys j0..j0+7 of row r
        int j0 = qd * 8;
        float sc[8];
#pragma unroll
        for (int jj = 0; jj < 8; jj++) sc[jj] = 0.f;
        const float4* q4 = (const float4*)(Qs + r*HD);
#pragma unroll 4
        for (int d4 = 0; d4 < 32; d4++) {
            float4 qv = q4[d4];
#pragma unroll
            for (int jj = 0; jj < 8; jj++) {
                float4 kv = ((const float4*)(Ks + (j0 + jj)*HD))[d4];
                sc[jj] += qv.x*kv.x + qv.y*kv.y + qv.z*kv.z + qv.w*kv.w;
            }
        }
#pragma unroll
        for (int jj = 0; jj < 8; jj++) {
            int kg = k0 + j0 + jj;
            sc[jj] = (kg <= q0 + r) ? sc[jj] * scale : -1e30f;
        }

        // register softmax across the row's 4 lanes
        float tmax = sc[0];
#pragma unroll
        for (int jj = 1; jj < 8; jj++) tmax = fmaxf(tmax, sc[jj]);
        tmax = fmaxf(tmax, __shfl_xor_sync(0xffffffffu, tmax, 1));
        tmax = fmaxf(tmax, __shfl_xor_sync(0xffffffffu, tmax, 2));
        float mn = fmaxf(m_reg, tmax);
        float al = __expf(m_reg - mn);
        float sum = 0.f;
#pragma unroll
        for (int jj = 0; jj < 8; jj++) {
            float p = __expf(sc[jj] - mn);
            Ss[r*33 + j0 + jj] = p;
            sum += p;
        }
        sum += __shfl_xor_sync(0xffffffffu, sum, 1);
        sum += __shfl_xor_sync(0xffffffffu, sum, 2);
        m_reg = mn;
        l_reg = l_reg * al + sum;

        __syncthreads();   // full P rows visible

        // rescale + P@V
#pragma unroll
        for (int i = 0; i < 32; i++) acc[i] *= al;
        const float* prow = Ss + r*33;
#pragma unroll 4
        for (int j = 0; j < 32; j++) {
            float p = prow[j];
            const float4* v4 = (const float4*)(Vs + j*HD + qd*32);
#pragma unroll
            for (int i4 = 0; i4 < 8; i4++) {
                float4 vv = v4[i4];
                acc[i4*4+0] = fmaf(p, vv.x, acc[i4*4+0]);
                acc[i4*4+1] = fmaf(p, vv.y, acc[i4*4+1]);
                acc[i4*4+2] = fmaf(p, vv.z, acc[i4*4+2]);
                acc[i4*4+3] = fmaf(p, vv.w, acc[i4*4+3]);
            }
        }
        __syncthreads();   // stage fully consumed before it is overwritten
    }

    float invl = 1.f / l_reg;
    uint2* o2 = (uint2*)(ah + (size_t)(b*SEQ + q0 + r) * HID + h*HD + qd*32);
#pragma unroll
    for (int i4 = 0; i4 < 8; i4++) {
        float4 o = make_float4(acc[i4*4+0]*invl, acc[i4*4+1]*invl,
                               acc[i4*4+2]*invl, acc[i4*4+3]*invl);
        o2[i4] = pack4h(o);
    }
}

// ------------------------- launch -------------------------
extern "C" void kernel_launch(void* const* d_in, const int* in_sizes, int n_in,
                              void* d_out, int out_size) {
    const int*   positions = (const int*)d_in[0];
    const float* hs        = (const float*)d_in[1];
    const float* ln1       = (const float*)d_in[2];
    const float* wqkv      = (const float*)d_in[3];
    const float* bqkv      = (const float*)d_in[4];
    const float* wo        = (const float*)d_in[5];
    const float* ln2       = (const float*)d_in[6];
    const float* w14       = (const float*)d_in[7];
    const float* w41       = (const float*)d_in[8];
    float* out = (float*)d_out;

    float *qkv, *attnout, *hidden;
    __half *wqkvh, *woh, *w14h, *w41h, *xh, *ah, *yh, *gh;
    cudaGetSymbolAddress((void**)&qkv,     g_qkv);
    cudaGetSymbolAddress((void**)&attnout, g_attnout);
    cudaGetSymbolAddress((void**)&hidden,  g_hidden);
    cudaGetSymbolAddress((void**)&wqkvh,   g_wqkvh);
    cudaGetSymbolAddress((void**)&woh,     g_woh);
    cudaGetSymbolAddress((void**)&w14h,    g_w14h);
    cudaGetSymbolAddress((void**)&w41h,    g_w41h);
    cudaGetSymbolAddress((void**)&xh,      g_xh);
    cudaGetSymbolAddress((void**)&ah,      g_ah);
    cudaGetSymbolAddress((void**)&yh,      g_yh);
    cudaGetSymbolAddress((void**)&gh,      g_gh);

    cudaFuncSetAttribute((const void*)&gemm_h<false>, cudaFuncAttributeMaxDynamicSharedMemorySize, GEMM_SMEM);
    cudaFuncSetAttribute((const void*)&gemm_h<true>,  cudaFuncAttributeMaxDynamicSharedMemorySize, GEMM_SMEM);
    cudaFuncSetAttribute(flash_attn_kernel, cudaFuncAttributeMaxDynamicSharedMemorySize, ATT_SMEM);

    // weight conversions (all plain fp16; w14 interleaved for SwiGLU fusion)
    {
        long long n4;
        n4 = (long long)QKV_DIM * HID / 4;
        round_f16_kernel<<<(unsigned)((n4+255)/256), 256>>>(wqkv, wqkvh, n4);
        n4 = (long long)HID * HID / 4;
        round_f16_kernel<<<(unsigned)((n4+255)/256), 256>>>(wo, woh, n4);
        n4 = (long long)(2*FFN) * HID / 4;
        round_f16_interleave_kernel<<<(unsigned)((n4+255)/256), 256>>>(w14, w14h, n4, HID/4);
        n4 = (long long)HID * FFN / 4;
        round_f16_kernel<<<(unsigned)((n4+255)/256), 256>>>(w41, w41h, n4);
    }

    // 1) xh = f16(rmsnorm(hs) * ln1)
    fused_norm_kernel<<<M_ROWS, 256>>>(nullptr, hs, ln1, nullptr, xh);

    // 2) qkv = x @ wqkv^T + bqkv
    gemm_h<false><<<16*36, 256, GEMM_SMEM>>>(xh, wqkvh, bqkv, nullptr, qkv, 36, HID, QKV_DIM);

    // 3) rope on q,k
    rope_kernel<<<dim3(M_ROWS, NH + NKV), 64>>>(positions, qkv);

    // 4) attention -> ah (fp16 ctx), cp.async-pipelined KV
    flash_attn_kernel<<<dim3(SEQ/32, NH, BATCH), 128, ATT_SMEM>>>(qkv, ah);

    // 5) attn_out = ctx @ wo^T
    gemm_h<false><<<16*32, 256, GEMM_SMEM>>>(ah, woh, nullptr, nullptr, attnout, 32, HID, HID);

    // 6) hidden = hs + attn_out ; yh = f16(rmsnorm(hidden) * ln2)
    fused_norm_kernel<<<M_ROWS, 256>>>(hs, attnout, ln2, hidden, yh);

    // 7) gh = f16(silu(a)*b) fused into FFN-up GEMM (interleaved w14, staged stores)
    gemm_h<true><<<16*214, 256, GEMM_SMEM>>>(yh, w14h, nullptr, nullptr, gh, 214, HID, 2*FFN);

    // 8) out = hidden + gated @ w41^T   (residual fused)
    gemm_h<false><<<16*32, 256, GEMM_SMEM>>>(gh, w41h, nullptr, hidden, out, 32, FFN, HID);
}

// round 17
// speedup vs baseline: 5.8824x; 2.7628x over previous
#include <cuda_runtime.h>
#include <cuda_fp16.h>
#include <math.h>
#include <stdint.h>

#define BATCH 2
#define SEQ 1024
#define HID 4096
#define NH 32
#define NKV 2
#define HD 128
#define FFN 13696
#define QKV_DIM ((NH + 2*NKV)*HD)   // 4608
#define M_ROWS (BATCH*SEQ)          // 2048
#define EPSV 1e-5f
#define V_OFF ((NH+NKV)*HD)         // 4352
#define K_OFF (NH*HD)               // 4096

// ------------------------- scratch (device globals) -------------------------
__device__ float g_qkv[(size_t)M_ROWS * QKV_DIM];
__device__ float g_attnout[(size_t)M_ROWS * HID];
__device__ float g_hidden[(size_t)M_ROWS * HID];
// fp16 weights (single plane). w14 rows PERMUTED: f -> 2f, FFN+f -> 2f+1.
__device__ __half g_wqkvh[(size_t)QKV_DIM * HID];
__device__ __half g_woh[(size_t)HID * HID];
__device__ __half g_w14h[(size_t)(2*FFN) * HID];
__device__ __half g_w41h[(size_t)HID * FFN];
// fp16 activations
__device__ __half g_xh[(size_t)M_ROWS * HID];
__device__ __half g_ah[(size_t)M_ROWS * HID];
__device__ __half g_yh[(size_t)M_ROWS * HID];
__device__ __half g_gh[(size_t)M_ROWS * FFN];
// attention inputs (fp16): roped q [M,NH*HD]; roped k [B,NKV,SEQ,HD]; vT [B,NKV,HD,SEQ]
__device__ __half g_qh[(size_t)M_ROWS * HID];
__device__ __half g_kh[(size_t)BATCH * NKV * SEQ * HD];
__device__ __half g_vT[(size_t)BATCH * NKV * HD * SEQ];

// ------------------------- PTX helpers -------------------------
__device__ __forceinline__ uint32_t smem_u32(const void* p) {
    uint32_t a;
    asm("{ .reg .u64 t; cvta.to.shared.u64 t, %1; cvt.u32.u64 %0, t; }" : "=r"(a) : "l"(p));
    return a;
}
__device__ __forceinline__ void cp16(uint32_t s, const void* g) {
    asm volatile("cp.async.cg.shared.global [%0], [%1], 16;" :: "r"(s), "l"(g));
}
__device__ __forceinline__ void ldsm4(uint32_t* r, uint32_t addr) {
    asm volatile("ldmatrix.sync.aligned.m8n8.x4.shared.b16 {%0,%1,%2,%3}, [%4];"
                 : "=r"(r[0]), "=r"(r[1]), "=r"(r[2]), "=r"(r[3]) : "r"(addr));
}
__device__ __forceinline__ void mma_f16(float* c, const uint32_t* a, uint32_t b0, uint32_t b1) {
    asm volatile(
        "mma.sync.aligned.m16n8k16.row.col.f32.f16.f16.f32 "
        "{%0,%1,%2,%3}, {%4,%5,%6,%7}, {%8,%9}, {%0,%1,%2,%3};"
        : "+f"(c[0]), "+f"(c[1]), "+f"(c[2]), "+f"(c[3])
        : "r"(a[0]), "r"(a[1]), "r"(a[2]), "r"(a[3]), "r"(b0), "r"(b1));
}

// ------------------------- misc helpers -------------------------
__device__ __forceinline__ float warp_sum(float v) {
#pragma unroll
    for (int o = 16; o > 0; o >>= 1) v += __shfl_xor_sync(0xffffffffu, v, o);
    return v;
}
__device__ __forceinline__ uint2 pack4h(float4 v) {
    union { uint2 u; __half h[4]; } H;
    H.h[0] = __float2half_rn(v.x); H.h[1] = __float2half_rn(v.y);
    H.h[2] = __float2half_rn(v.z); H.h[3] = __float2half_rn(v.w);
    return H.u;
}
__device__ __forceinline__ uint32_t pack2h(float x, float y) {
    __half2 h = __floats2half2_rn(x, y);
    return *(uint32_t*)&h;
}

// ------------------------- weight conversion kernels -------------------------
__global__ void round_f16_kernel(const float* __restrict__ in,
                                 __half* __restrict__ out, long long n4) {
    long long i = (long long)blockIdx.x * blockDim.x + threadIdx.x;
    if (i >= n4) return;
    ((uint2*)out)[i] = pack4h(((const float4*)in)[i]);
}
__global__ void round_f16_interleave_kernel(const float* __restrict__ in,
                                            __half* __restrict__ out,
                                            long long n4, int kq) {
    long long i = (long long)blockIdx.x * blockDim.x + threadIdx.x;
    if (i >= n4) return;
    long long n = i / kq;
    long long k4 = i - n * kq;
    long long nn = (n < FFN) ? 2*n : 2*(n - FFN) + 1;
    ((uint2*)out)[nn * kq + k4] = pack4h(((const float4*)in)[i]);
}

// ------------------------- fused (add+)rmsnorm -> fp16 single -------------------------
__global__ void __launch_bounds__(256) fused_norm_kernel(
    const float* __restrict__ res, const float* __restrict__ x,
    const float* __restrict__ w, float* __restrict__ hid_out,
    __half* __restrict__ yh) {
    __shared__ __align__(16) float buf[HID];
    __shared__ float red[8];
    int row = blockIdx.x;
    size_t base = (size_t)row * HID;
    const float4* x4 = (const float4*)(x + base);
    const float4* r4 = res ? (const float4*)(res + base) : nullptr;
    float4* b4 = (float4*)buf;

    float ss = 0.f;
    for (int i = threadIdx.x; i < HID/4; i += 256) {
        float4 v = x4[i];
        if (r4) { float4 rr = r4[i]; v.x += rr.x; v.y += rr.y; v.z += rr.z; v.w += rr.w; }
        b4[i] = v;
        ss += v.x*v.x + v.y*v.y + v.z*v.z + v.w*v.w;
    }
    ss = warp_sum(ss);
    if ((threadIdx.x & 31) == 0) red[threadIdx.x >> 5] = ss;
    __syncthreads();
    float tot = 0.f;
#pragma unroll
    for (int i = 0; i < 8; i++) tot += red[i];
    float inv = rsqrtf(tot / (float)HID + EPSV);

    float4* h4 = hid_out ? (float4*)(hid_out + base) : nullptr;
    const float4* w4 = (const float4*)w;
    uint2* y2 = (uint2*)(yh + base);
    for (int i = threadIdx.x; i < HID/4; i += 256) {
        float4 v = b4[i];
        if (h4) h4[i] = v;
        float4 ww = w4[i];
        float4 o;
        o.x = v.x * inv * ww.x; o.y = v.y * inv * ww.y;
        o.z = v.z * inv * ww.z; o.w = v.w * inv * ww.w;
        y2[i] = pack4h(o);
    }
}

// ------------------------- fp16 1-phase HMMA GEMM -------------------------
#define NSTAGE 3
#define STAGE_BYTES 32768
#define GEMM_SMEM (NSTAGE * STAGE_BYTES + 1024)
#define SWI_STRIDE 72

template<bool SWI>
__global__ void __launch_bounds__(256, 2) gemm_h(
    const __half* __restrict__ Av, const __half* __restrict__ Bv,
    const float* __restrict__ bias, const float* __restrict__ resid,
    void* __restrict__ Cv, int NT, int Kel, int N) {
    extern __shared__ char smem[];
    uint32_t dataA = (smem_u32(smem) + 1023) & ~1023u;
    int tid = threadIdx.x;
    int wid = tid >> 5, lane = tid & 31;

    int g = blockIdx.x / (16*18);
    int r = blockIdx.x % (16*18);
    int gn = NT - g*18; if (gn > 18) gn = 18;
    int bn = (g*18 + r % gn) * 128;
    int bm = (r / gn) * 128;

    const size_t rowb = (size_t)Kel * 2;
    const char* Abase = (const char*)Av + (size_t)bm * rowb;
    const char* Bbase = (const char*)Bv + (size_t)bn * rowb;
    const int NC = Kel >> 6;
    const int c16 = (tid & 7) * 16;
    const int row0 = tid >> 3;

    auto load_chunk = [&](int j) {
        size_t off = (size_t)j * 128 + c16;
        int s = j % NSTAGE;
        uint32_t sA = dataA + s*STAGE_BYTES;
        uint32_t sB = sA + 16384;
#pragma unroll
        for (int p = 0; p < 4; p++) {
            int row = row0 + p*32;
            uint32_t sw = row*128 + (c16 ^ ((row & 7) << 4));
            cp16(sA + sw, Abase + (size_t)row * rowb + off);
            cp16(sB + sw, Bbase + (size_t)row * rowb + off);
        }
        asm volatile("cp.async.commit_group;" ::: "memory");
    };

    float acc[4][4][4];
#pragma unroll
    for (int a = 0; a < 4; a++)
#pragma unroll
        for (int b = 0; b < 4; b++)
#pragma unroll
            for (int c = 0; c < 4; c++) acc[a][b][c] = 0.f;

    const int warp_m = (wid & 1) * 64;
    const int warp_n = (wid >> 1) * 32;

    load_chunk(0);
    load_chunk(1);

    for (int i = 0; i < NC; i++) {
        asm volatile("cp.async.wait_group 1;" ::: "memory");
        __syncthreads();

        uint32_t sA = dataA + (i % NSTAGE)*STAGE_BYTES;
        uint32_t sB = sA + 16384;
#pragma unroll
        for (int ks = 0; ks < 4; ks++) {
            int kb = ks * 32;
            uint32_t af[4][4];
#pragma unroll
            for (int mt = 0; mt < 4; mt++) {
                int rw = warp_m + mt*16 + (lane & 15);
                int cb = kb + ((lane >> 4) << 4);
                ldsm4(af[mt], sA + rw*128 + (cb ^ ((rw & 7) << 4)));
            }
            uint32_t bf[2][4];
#pragma unroll
            for (int nt = 0; nt < 2; nt++) {
                int nr = warp_n + nt*16 + ((lane >> 4) << 3) + (lane & 7);
                int cb = kb + (((lane >> 3) & 1) << 4);
                ldsm4(bf[nt], sB + nr*128 + (cb ^ ((nr & 7) << 4)));
            }
#pragma unroll
            for (int mt = 0; mt < 4; mt++) {
#pragma unroll
                for (int nj = 0; nj < 4; nj++) {
                    const uint32_t* bb = bf[nj >> 1];
                    uint32_t b0 = (nj & 1) ? bb[2] : bb[0];
                    uint32_t b1 = (nj & 1) ? bb[3] : bb[1];
                    mma_f16(acc[mt][nj], af[mt], b0, b1);
                }
            }
        }
        if (i + 2 < NC) load_chunk(i + 2);
        else asm volatile("cp.async.commit_group;" ::: "memory");
    }

    if (SWI) {
        asm volatile("cp.async.wait_group 0;" ::: "memory");
        __syncthreads();
        __half* stage = (__half*)(smem + (dataA - smem_u32(smem)));
#pragma unroll
        for (int mt = 0; mt < 4; mt++) {
            int rr = warp_m + mt*16 + (lane >> 2);
#pragma unroll
            for (int nj = 0; nj < 4; nj++) {
                int hc = (warp_n >> 1) + nj*4 + (lane & 3);
                float a0 = acc[mt][nj][0], b0v = acc[mt][nj][1];
                float a1 = acc[mt][nj][2], b1v = acc[mt][nj][3];
                stage[rr * SWI_STRIDE + hc] =
                    __float2half_rn((a0 / (1.f + __expf(-a0))) * b0v);
                stage[(rr + 8) * SWI_STRIDE + hc] =
                    __float2half_rn((a1 / (1.f + __expf(-a1))) * b1v);
            }
        }
        __syncthreads();
        __half* G = (__half*)Cv;
        const int Nh = N >> 1;
        for (int t = tid; t < 128*8; t += 256) {
            int row = t >> 3, seg = t & 7;
            uint4 v = *(const uint4*)(stage + row * SWI_STRIDE + seg*8);
            *(uint4*)(G + (size_t)(bm + row) * Nh + (bn >> 1) + seg*8) = v;
        }
    } else {
#pragma unroll
        for (int mt = 0; mt < 4; mt++) {
            int row0g = bm + warp_m + mt*16 + (lane >> 2);
#pragma unroll
            for (int nj = 0; nj < 4; nj++) {
                int col = bn + warp_n + nj*8 + (lane & 3)*2;
                float* C = (float*)Cv;
                float b0 = 0.f, b1 = 0.f;
                if (bias) { b0 = bias[col]; b1 = bias[col+1]; }
                float* p0 = C + (size_t)row0g * N + col;
                float* p1 = C + (size_t)(row0g + 8) * N + col;
                float2 v0 = make_float2(acc[mt][nj][0] + b0, acc[mt][nj][1] + b1);
                float2 v1 = make_float2(acc[mt][nj][2] + b0, acc[mt][nj][3] + b1);
                if (resid) {
                    float2 r0 = *(const float2*)(resid + (size_t)row0g * N + col);
                    float2 r1 = *(const float2*)(resid + (size_t)(row0g + 8) * N + col);
                    v0.x += r0.x; v0.y += r0.y; v1.x += r1.x; v1.y += r1.y;
                }
                *(float2*)p0 = v0;
                *(float2*)p1 = v1;
            }
        }
    }
}

// ------------------------- rope + fp16 convert (q,k) -------------------------
__global__ void rope_convert_kernel(const int* __restrict__ positions,
                                    const float* __restrict__ qkv,
                                    __half* __restrict__ qh,
                                    __half* __restrict__ kh) {
    int bs = blockIdx.x;
    int hh = blockIdx.y;        // 0..NH-1 q heads, NH..NH+NKV-1 k heads
    int i  = threadIdx.x;
    const float* base = qkv + (size_t)bs * QKV_DIM + hh * HD;   // q at hh*HD, k contiguous after
    float pos = (float)positions[bs];
    float freq = __expf(-(float)i * 0.14391565217f);
    float ang = pos * freq;
    float sn, cs;
    sincosf(ang, &sn, &cs);
    float x1 = base[i];
    float x2 = base[i + 64];
    float o1 = x1 * cs - x2 * sn;
    float o2 = x2 * cs + x1 * sn;
    __half* dst;
    if (hh < NH) {
        dst = qh + (size_t)bs * HID + hh * HD;
    } else {
        int b = bs / SEQ, s = bs - b * SEQ;
        dst = kh + ((size_t)(b*NKV + (hh - NH)) * SEQ + s) * HD;
    }
    dst[i]      = __float2half_rn(o1);
    dst[i + 64] = __float2half_rn(o2);
}

// ------------------------- v transpose -> fp16 [b][kv][dim][seq] -------------------------
__global__ void __launch_bounds__(256) transpose_v_kernel(
    const float* __restrict__ qkv, __half* __restrict__ vT) {
    __shared__ float t[32][33];
    int s0 = blockIdx.x * 32;
    int d0 = blockIdx.y * 32;
    int bk = blockIdx.z;
    int b = bk >> 1, kvh = bk & 1;
    int tid = threadIdx.x;
    for (int i = tid; i < 32*32; i += 256) {
        int si = i >> 5, di = i & 31;
        t[si][di] = qkv[(size_t)(b*SEQ + s0 + si) * QKV_DIM + V_OFF + kvh*HD + d0 + di];
    }
    __syncthreads();
    for (int i = tid; i < 32*32; i += 256) {
        int di = i >> 5, si = i & 31;
        vT[((size_t)bk * HD + d0 + di) * SEQ + s0 + si] = __float2half_rn(t[si][di]);
    }
}

// ------------------------- HMMA flash attention -------------------------
// 64 q-rows/block, 128 thr = 4 warps (16 rows each). Double-buffered K+V stages.
// smem: Q 64x256B | stage{K 32x256B, vT 128x80B} x2
#define ATT_SMEM (16384 + 2*(8192 + 10240))

__global__ void __launch_bounds__(128) flash_attn_kernel(
    const __half* __restrict__ qh, const __half* __restrict__ kh,
    const __half* __restrict__ vT, __half* __restrict__ ah) {
    extern __shared__ char smattn[];
    uint32_t Qb = smem_u32(smattn);
    int qt = blockIdx.x, h = blockIdx.y, b = blockIdx.z;
    int kvh = h >> 4;
    int tid = threadIdx.x, wid = tid >> 5, lane = tid & 31;
    int q0 = qt * 64;
    const int nkt = 2*qt + 2;

    const __half* Kg = kh + (size_t)(b*NKV + kvh) * SEQ * HD;
    const __half* Vg = vT + (size_t)(b*NKV + kvh) * HD * SEQ;

    // Q load (joins group 0 with tile 0)
    for (int i = tid; i < 64*16; i += 128) {
        int row = i >> 4, c16 = (i & 15) * 16;
        cp16(Qb + row*256 + (c16 ^ ((row & 7) << 4)),
             (const char*)(qh + (size_t)(b*SEQ + q0 + row) * HID + h*HD) + c16);
    }
    auto load_kv = [&](int kt, int s) {
        uint32_t Kb = Qb + 16384 + s * 18432;
        uint32_t Vb = Kb + 8192;
        int k0 = kt * 32;
        for (int i = tid; i < 512; i += 128) {
            int row = i >> 4, c16 = (i & 15) * 16;
            cp16(Kb + row*256 + (c16 ^ ((row & 7) << 4)),
                 (const char*)(Kg + (size_t)(k0 + row) * HD) + c16);
        }
        for (int i = tid; i < 512; i += 128) {
            int row = i >> 2, c16 = (i & 3) * 16;
            cp16(Vb + row*80 + c16,
                 (const char*)(Vg + (size_t)row * SEQ + k0) + c16);
        }
        asm volatile("cp.async.commit_group;" ::: "memory");
    };
    load_kv(0, 0);

    const int r0 = wid * 16;
    float m1 = -1e30f, m2 = -1e30f, l1 = 0.f, l2 = 0.f;
    float acc[16][4];
#pragma unroll
    for (int i = 0; i < 16; i++)
#pragma unroll
        for (int c = 0; c < 4; c++) acc[i][c] = 0.f;

    const float scale = 0.08838834764831845f;

    for (int kt = 0; kt < nkt; kt++) {
        int cur = kt & 1;
        if (kt + 1 < nkt) {
            load_kv(kt + 1, cur ^ 1);
            asm volatile("cp.async.wait_group 1;" ::: "memory");
        } else {
            asm volatile("cp.async.wait_group 0;" ::: "memory");
        }
        __syncthreads();

        uint32_t Kb = Qb + 16384 + cur * 18432;
        uint32_t Vb = Kb + 8192;
        int k0 = kt * 32;

        // scores: S[16 rows][32 keys] in frags sf[nj][c]
        float sf[4][4];
#pragma unroll
        for (int nj = 0; nj < 4; nj++)
#pragma unroll
            for (int c = 0; c < 4; c++) sf[nj][c] = 0.f;
#pragma unroll
        for (int ks = 0; ks < 8; ks++) {
            uint32_t aq[4];
            int rw = r0 + (lane & 15);
            int cb = ks*32 + ((lane >> 4) << 4);
            ldsm4(aq, Qb + rw*256 + (cb ^ ((rw & 7) << 4)));
#pragma unroll
            for (int nt = 0; nt < 2; nt++) {
                uint32_t bk[4];
                int nr = nt*16 + ((lane >> 4) << 3) + (lane & 7);
                int cbb = ks*32 + (((lane >> 3) & 1) << 4);
                ldsm4(bk, Kb + nr*256 + (cbb ^ ((nr & 7) << 4)));
                mma_f16(sf[nt*2],   aq, bk[0], bk[1]);
                mma_f16(sf[nt*2+1], aq, bk[2], bk[3]);
            }
        }

        // scale + causal mask
        int gr1 = q0 + r0 + (lane >> 2);
        if (k0 + 31 <= gr1) {          // fully valid for both rows of this thread
#pragma unroll
            for (int nj = 0; nj < 4; nj++)
#pragma unroll
                for (int c = 0; c < 4; c++) sf[nj][c] *= scale;
        } else {
#pragma unroll
            for (int nj = 0; nj < 4; nj++) {
                int c0 = k0 + nj*8 + 2*(lane & 3);
#pragma unroll
                for (int cc = 0; cc < 2; cc++) {
                    sf[nj][cc]   = (c0+cc <= gr1)   ? sf[nj][cc]*scale   : -1e30f;
                    sf[nj][cc+2] = (c0+cc <= gr1+8) ? sf[nj][cc+2]*scale : -1e30f;
                }
            }
        }

        // register softmax (rows r1 = gr1, r2 = gr1+8), reduce over 4 lanes
        float tm1 = -1e30f, tm2 = -1e30f;
#pragma unroll
        for (int nj = 0; nj < 4; nj++) {
            tm1 = fmaxf(tm1, fmaxf(sf[nj][0], sf[nj][1]));
            tm2 = fmaxf(tm2, fmaxf(sf[nj][2], sf[nj][3]));
        }
        tm1 = fmaxf(tm1, __shfl_xor_sync(0xffffffffu, tm1, 1));
        tm1 = fmaxf(tm1, __shfl_xor_sync(0xffffffffu, tm1, 2));
        tm2 = fmaxf(tm2, __shfl_xor_sync(0xffffffffu, tm2, 1));
        tm2 = fmaxf(tm2, __shfl_xor_sync(0xffffffffu, tm2, 2));
        float mn1 = fmaxf(m1, tm1), mn2 = fmaxf(m2, tm2);
        float al1 = __expf(m1 - mn1), al2 = __expf(m2 - mn2);
        float s1 = 0.f, s2 = 0.f;
#pragma unroll
        for (int nj = 0; nj < 4; nj++) {
            sf[nj][0] = __expf(sf[nj][0] - mn1); s1 += sf[nj][0];
            sf[nj][1] = __expf(sf[nj][1] - mn1); s1 += sf[nj][1];
            sf[nj][2] = __expf(sf[nj][2] - mn2); s2 += sf[nj][2];
            sf[nj][3] = __expf(sf[nj][3] - mn2); s2 += sf[nj][3];
        }
        s1 += __shfl_xor_sync(0xffffffffu, s1, 1);
        s1 += __shfl_xor_sync(0xffffffffu, s1, 2);
        s2 += __shfl_xor_sync(0xffffffffu, s2, 1);
        s2 += __shfl_xor_sync(0xffffffffu, s2, 2);
        m1 = mn1; m2 = mn2;
        l1 = l1 * al1 + s1;
        l2 = l2 * al2 + s2;

        // rescale acc
#pragma unroll
        for (int nt = 0; nt < 16; nt++) {
            acc[nt][0] *= al1; acc[nt][1] *= al1;
            acc[nt][2] *= al2; acc[nt][3] *= al2;
        }

        // PV: P (frag registers) @ V (vT smem, pitch 80B)
#pragma unroll
        for (int kc = 0; kc < 2; kc++) {
            uint32_t ap[4];
            ap[0] = pack2h(sf[kc*2][0],   sf[kc*2][1]);
            ap[1] = pack2h(sf[kc*2][2],   sf[kc*2][3]);
            ap[2] = pack2h(sf[kc*2+1][0], sf[kc*2+1][1]);
            ap[3] = pack2h(sf[kc*2+1][2], sf[kc*2+1][3]);
#pragma unroll
            for (int nt2 = 0; nt2 < 8; nt2++) {
                uint32_t bv[4];
                int nr = nt2*16 + ((lane >> 4) << 3) + (lane & 7);
                int cb = kc*32 + (((lane >> 3) & 1) << 4);
                ldsm4(bv, Vb + nr*80 + cb);
                mma_f16(acc[nt2*2],   ap, bv[0], bv[1]);
                mma_f16(acc[nt2*2+1], ap, bv[2], bv[3]);
            }
        }
        __syncthreads();   // stage fully consumed before overwrite
    }

    float i1 = 1.f / l1, i2 = 1.f / l2;
    size_t rb1 = (size_t)(b*SEQ + q0 + r0 + (lane >> 2)) * HID + h*HD;
    size_t rb2 = rb1 + (size_t)8 * HID;
#pragma unroll
    for (int nt = 0; nt < 16; nt++) {
        int d0 = nt*8 + 2*(lane & 3);
        *(uint32_t*)(ah + rb1 + d0) = pack2h(acc[nt][0]*i1, acc[nt][1]*i1);
        *(uint32_t*)(ah + rb2 + d0) = pack2h(acc[nt][2]*i2, acc[nt][3]*i2);
    }
}

// ------------------------- launch -------------------------
extern "C" void kernel_launch(void* const* d_in, const int* in_sizes, int n_in,
                              void* d_out, int out_size) {
    const int*   positions = (const int*)d_in[0];
    const float* hs        = (const float*)d_in[1];
    const float* ln1       = (const float*)d_in[2];
    const float* wqkv      = (const float*)d_in[3];
    const float* bqkv      = (const float*)d_in[4];
    const float* wo        = (const float*)d_in[5];
    const float* ln2       = (const float*)d_in[6];
    const float* w14       = (const float*)d_in[7];
    const float* w41       = (const float*)d_in[8];
    float* out = (float*)d_out;

    float *qkv, *attnout, *hidden;
    __half *wqkvh, *woh, *w14h, *w41h, *xh, *ah, *yh, *gh, *qh, *kh, *vT;
    cudaGetSymbolAddress((void**)&qkv,     g_qkv);
    cudaGetSymbolAddress((void**)&attnout, g_attnout);
    cudaGetSymbolAddress((void**)&hidden,  g_hidden);
    cudaGetSymbolAddress((void**)&wqkvh,   g_wqkvh);
    cudaGetSymbolAddress((void**)&woh,     g_woh);
    cudaGetSymbolAddress((void**)&w14h,    g_w14h);
    cudaGetSymbolAddress((void**)&w41h,    g_w41h);
    cudaGetSymbolAddress((void**)&xh,      g_xh);
    cudaGetSymbolAddress((void**)&ah,      g_ah);
    cudaGetSymbolAddress((void**)&yh,      g_yh);
    cudaGetSymbolAddress((void**)&gh,      g_gh);
    cudaGetSymbolAddress((void**)&qh,      g_qh);
    cudaGetSymbolAddress((void**)&kh,      g_kh);
    cudaGetSymbolAddress((void**)&vT,      g_vT);

    cudaFuncSetAttribute((const void*)&gemm_h<false>, cudaFuncAttributeMaxDynamicSharedMemorySize, GEMM_SMEM);
    cudaFuncSetAttribute((const void*)&gemm_h<true>,  cudaFuncAttributeMaxDynamicSharedMemorySize, GEMM_SMEM);
    cudaFuncSetAttribute(flash_attn_kernel, cudaFuncAttributeMaxDynamicSharedMemorySize, ATT_SMEM);

    // weight conversions
    {
        long long n4;
        n4 = (long long)QKV_DIM * HID / 4;
        round_f16_kernel<<<(unsigned)((n4+255)/256), 256>>>(wqkv, wqkvh, n4);
        n4 = (long long)HID * HID / 4;
        round_f16_kernel<<<(unsigned)((n4+255)/256), 256>>>(wo, woh, n4);
        n4 = (long long)(2*FFN) * HID / 4;
        round_f16_interleave_kernel<<<(unsigned)((n4+255)/256), 256>>>(w14, w14h, n4, HID/4);
        n4 = (long long)HID * FFN / 4;
        round_f16_kernel<<<(unsigned)((n4+255)/256), 256>>>(w41, w41h, n4);
    }

    // 1) xh = f16(rmsnorm(hs) * ln1)
    fused_norm_kernel<<<M_ROWS, 256>>>(nullptr, hs, ln1, nullptr, xh);

    // 2) qkv = x @ wqkv^T + bqkv (fp32 out)
    gemm_h<false><<<16*36, 256, GEMM_SMEM>>>(xh, wqkvh, bqkv, nullptr, qkv, 36, HID, QKV_DIM);

    // 3a) rope q,k -> fp16 buffers ; 3b) v -> fp16 transposed
    rope_convert_kernel<<<dim3(M_ROWS, NH + NKV), 64>>>(positions, qkv, qh, kh);
    transpose_v_kernel<<<dim3(SEQ/32, HD/32, BATCH*NKV), 256>>>(qkv, vT);

    // 4) HMMA flash attention -> ah
    flash_attn_kernel<<<dim3(SEQ/64, NH, BATCH), 128, ATT_SMEM>>>(qh, kh, vT, ah);

    // 5) attn_out = ctx @ wo^T
    gemm_h<false><<<16*32, 256, GEMM_SMEM>>>(ah, woh, nullptr, nullptr, attnout, 32, HID, HID);

    // 6) hidden = hs + attn_out ; yh = f16(rmsnorm(hidden) * ln2)
    fused_norm_kernel<<<M_ROWS, 256>>>(hs, attnout, ln2, hidden, yh);

    // 7) gh = f16(silu(a)*b) fused into FFN-up GEMM
    gemm_h<true><<<16*214, 256, GEMM_SMEM>>>(yh, w14h, nullptr, nullptr, gh, 214, HID, 2*FFN);

    // 8) out = hidden + gated @ w41^T
    gemm_h<false><<<16*32, 256, GEMM_SMEM>>>(gh, w41h, nullptr, hidden, out, 32, FFN, HID);
}